// round 1
// baseline (speedup 1.0000x reference)
#include <cuda_runtime.h>
#include <math.h>

// Problem constants
#define BB    4
#define NQ    4096
#define CC    512
#define HEADS 8
#define DH    64
#define NKV   256      // (64/4)^2
#define KSPLIT 4
#define KCONV 8192     // 4*4*512

// ---------------------------------------------------------------------------
// Scratch (static device globals; no allocation allowed)
// ---------------------------------------------------------------------------
__device__ float g_q[BB * NQ * CC];                 // Q projection  [16384,512]
__device__ float g_xr_part[KSPLIT * BB * NKV * CC]; // conv split-K partials
__device__ float g_xr[BB * NKV * CC];               // layernormed reduced tokens
__device__ float g_k[BB * NKV * CC];                // K projection  [1024,512]
__device__ float g_v[BB * NKV * CC];                // V projection  [1024,512]
__device__ float g_attn[BB * NQ * CC];              // attention out [16384,512]

// ---------------------------------------------------------------------------
// Generic 128x128x8 fp32 GEMM tile: C[M,N] = A[M,K] @ B[K,N] + bias
// 256 threads, 8x8 per thread. Requires M%128==0, N%128==0, K%8==0.
// ---------------------------------------------------------------------------
__device__ __forceinline__ void sgemm_tile(
    const float* __restrict__ A, const float* __restrict__ Bm,
    const float* __restrict__ bias, float* __restrict__ Cm,
    const int Nn, const int K, const int bm, const int bn)
{
    __shared__ float As[8][132];   // padded: avoids 2-way store conflicts
    __shared__ float Bs[8][128];

    const int tid  = threadIdx.x;
    const int arow = tid >> 1;
    const int acol = (tid & 1) << 2;
    const int brow = tid >> 5;
    const int bcol = (tid & 31) << 2;
    const int ty   = (tid >> 4) << 3;
    const int tx   = (tid & 15) << 3;

    float acc[8][8];
#pragma unroll
    for (int i = 0; i < 8; ++i)
#pragma unroll
        for (int j = 0; j < 8; ++j) acc[i][j] = 0.f;

    const float* Ap = A + (size_t)(bm + arow) * K + acol;
    const float* Bp = Bm + (size_t)brow * Nn + bn + bcol;

    float4 av = *(const float4*)Ap;
    float4 bv = *(const float4*)Bp;

    for (int k0 = 0; k0 < K; k0 += 8) {
        __syncthreads();
        As[acol + 0][arow] = av.x;
        As[acol + 1][arow] = av.y;
        As[acol + 2][arow] = av.z;
        As[acol + 3][arow] = av.w;
        *(float4*)&Bs[brow][bcol] = bv;
        __syncthreads();
        if (k0 + 8 < K) {
            av = *(const float4*)(Ap + k0 + 8);
            bv = *(const float4*)(Bp + (size_t)(k0 + 8) * Nn);
        }
#pragma unroll
        for (int kk = 0; kk < 8; ++kk) {
            float af[8], bf[8];
            *(float4*)&af[0] = *(const float4*)&As[kk][ty];
            *(float4*)&af[4] = *(const float4*)&As[kk][ty + 4];
            *(float4*)&bf[0] = *(const float4*)&Bs[kk][tx];
            *(float4*)&bf[4] = *(const float4*)&Bs[kk][tx + 4];
#pragma unroll
            for (int i = 0; i < 8; ++i)
#pragma unroll
                for (int j = 0; j < 8; ++j)
                    acc[i][j] += af[i] * bf[j];
        }
    }

#pragma unroll
    for (int i = 0; i < 8; ++i) {
        const size_t row = (size_t)(bm + ty + i);
#pragma unroll
        for (int j = 0; j < 8; j += 4) {
            const int col = bn + tx + j;
            float4 o;
            o.x = acc[i][j + 0] + bias[col + 0];
            o.y = acc[i][j + 1] + bias[col + 1];
            o.z = acc[i][j + 2] + bias[col + 2];
            o.w = acc[i][j + 3] + bias[col + 3];
            *(float4*)&Cm[row * Nn + col] = o;
        }
    }
}

// Q projection: g_q = x @ wq + bq          grid(4,128)
__global__ void qproj_kernel(const float* __restrict__ x,
                             const float* __restrict__ wq,
                             const float* __restrict__ bq)
{
    sgemm_tile(x, wq, bq, g_q, CC, CC, blockIdx.y * 128, blockIdx.x * 128);
}

// K and V projections from g_xr: grid(8,8); blockIdx.x>=4 -> V
__global__ void kv_gemm_kernel(const float* __restrict__ wk,
                               const float* __restrict__ bk,
                               const float* __restrict__ wv,
                               const float* __restrict__ bv)
{
    const int sel = blockIdx.x >> 2;
    const int bn  = (blockIdx.x & 3) * 128;
    sgemm_tile(g_xr, sel ? wv : wk, sel ? bv : bk, sel ? g_v : g_k,
               CC, CC, blockIdx.y * 128, bn);
}

// Output projection: out = g_attn @ wp + bp    grid(4,128)
__global__ void outproj_kernel(const float* __restrict__ wp,
                               const float* __restrict__ bp,
                               float* __restrict__ out)
{
    sgemm_tile(g_attn, wp, bp, out, CC, CC, blockIdx.y * 128, blockIdx.x * 128);
}

// ---------------------------------------------------------------------------
// Conv (stride=kernel=4, VALID) as split-K patch GEMM:
//   A[p, kidx]  with p=(b,oh,ow), kidx=(kh,kw,ci);  W flat [8192, 512]
// grid(4, 8, KSPLIT), each z handles 2048 of K into its own partial buffer.
// ---------------------------------------------------------------------------
__global__ void conv_gemm_kernel(const float* __restrict__ x,
                                 const float* __restrict__ w_sr)
{
    __shared__ float As[8][132];
    __shared__ float Bs[8][128];

    const int tid   = threadIdx.x;
    const int bm    = blockIdx.y * 128;
    const int bn    = blockIdx.x * 128;
    const int kbase = blockIdx.z * (KCONV / KSPLIT);
    float* Cm = g_xr_part + (size_t)blockIdx.z * (BB * NKV * CC);

    const int arow = tid >> 1;
    const int acol = (tid & 1) << 2;
    const int brow = tid >> 5;
    const int bcol = (tid & 31) << 2;
    const int ty   = (tid >> 4) << 3;
    const int tx   = (tid & 15) << 3;

    // decode patch row
    const int r  = bm + arow;
    const int b  = r >> 8;
    const int oh = (r >> 4) & 15;
    const int ow = r & 15;

    float acc[8][8];
#pragma unroll
    for (int i = 0; i < 8; ++i)
#pragma unroll
        for (int j = 0; j < 8; ++j) acc[i][j] = 0.f;

    int kidx = kbase + acol;
    int kh = kidx >> 11, kw = (kidx >> 9) & 3, ci = kidx & 511;
    float4 av = *(const float4*)&x[((size_t)(b * 4096 + (oh * 4 + kh) * 64 + ow * 4 + kw)) * 512 + ci];
    float4 bv = *(const float4*)&w_sr[(size_t)(kbase + brow) * 512 + bn + bcol];

    const int KLEN = KCONV / KSPLIT;  // 2048
    for (int k0 = 0; k0 < KLEN; k0 += 8) {
        __syncthreads();
        As[acol + 0][arow] = av.x;
        As[acol + 1][arow] = av.y;
        As[acol + 2][arow] = av.z;
        As[acol + 3][arow] = av.w;
        *(float4*)&Bs[brow][bcol] = bv;
        __syncthreads();
        if (k0 + 8 < KLEN) {
            kidx = kbase + k0 + 8 + acol;
            kh = kidx >> 11; kw = (kidx >> 9) & 3; ci = kidx & 511;
            av = *(const float4*)&x[((size_t)(b * 4096 + (oh * 4 + kh) * 64 + ow * 4 + kw)) * 512 + ci];
            bv = *(const float4*)&w_sr[(size_t)(kbase + k0 + 8 + brow) * 512 + bn + bcol];
        }
#pragma unroll
        for (int kk = 0; kk < 8; ++kk) {
            float af[8], bf[8];
            *(float4*)&af[0] = *(const float4*)&As[kk][ty];
            *(float4*)&af[4] = *(const float4*)&As[kk][ty + 4];
            *(float4*)&bf[0] = *(const float4*)&Bs[kk][tx];
            *(float4*)&bf[4] = *(const float4*)&Bs[kk][tx + 4];
#pragma unroll
            for (int i = 0; i < 8; ++i)
#pragma unroll
                for (int j = 0; j < 8; ++j)
                    acc[i][j] += af[i] * bf[j];
        }
    }

#pragma unroll
    for (int i = 0; i < 8; ++i) {
        const size_t row = (size_t)(bm + ty + i);
#pragma unroll
        for (int j = 0; j < 8; j += 4) {
            *(float4*)&Cm[row * 512 + bn + tx + j] =
                make_float4(acc[i][j], acc[i][j + 1], acc[i][j + 2], acc[i][j + 3]);
        }
    }
}

// ---------------------------------------------------------------------------
// Reduce split-K partials + bias, then LayerNorm over C=512.
// grid(1024), 128 threads; each thread owns 4 columns.
// ---------------------------------------------------------------------------
__global__ void ln_kernel(const float* __restrict__ bsr,
                          const float* __restrict__ gamma,
                          const float* __restrict__ beta)
{
    const int r   = blockIdx.x;
    const int tid = threadIdx.x;

    float v[4];
    float s1 = 0.f, s2 = 0.f;
#pragma unroll
    for (int i = 0; i < 4; ++i) {
        const int c = tid + i * 128;
        const size_t off = (size_t)r * 512 + c;
        float t = g_xr_part[off]
                + g_xr_part[(size_t)1 * BB * NKV * CC + off]
                + g_xr_part[(size_t)2 * BB * NKV * CC + off]
                + g_xr_part[(size_t)3 * BB * NKV * CC + off]
                + bsr[c];
        v[i] = t;
        s1 += t;
        s2 += t * t;
    }
#pragma unroll
    for (int o = 16; o > 0; o >>= 1) {
        s1 += __shfl_xor_sync(0xffffffffu, s1, o);
        s2 += __shfl_xor_sync(0xffffffffu, s2, o);
    }
    __shared__ float red[8];
    const int warp = tid >> 5, lane = tid & 31;
    if (lane == 0) { red[warp] = s1; red[warp + 4] = s2; }
    __syncthreads();
    s1 = red[0] + red[1] + red[2] + red[3];
    s2 = red[4] + red[5] + red[6] + red[7];

    const float mu   = s1 * (1.f / 512.f);
    const float var  = s2 * (1.f / 512.f) - mu * mu;
    const float rstd = rsqrtf(var + 1e-5f);

#pragma unroll
    for (int i = 0; i < 4; ++i) {
        const int c = tid + i * 128;
        g_xr[(size_t)r * 512 + c] = (v[i] - mu) * rstd * gamma[c] + beta[c];
    }
}

// ---------------------------------------------------------------------------
// Attention: one CTA per (q-tile of 64, b*H).  Full K/V/S in smem (n_kv=256),
// exact softmax, O written directly in [b, q, h*64+d] layout.
// ---------------------------------------------------------------------------
#define SPAD 264
#define ATT_SMEM ((64 * 64 + 64 * 256 + 256 * 64 + 64 * SPAD) * 4)

__global__ void attn_kernel()
{
    extern __shared__ float sm[];
    float* Qs = sm;                  // [64][64]   Qs[d*64+q]
    float* Ks = Qs + 64 * 64;        // [64][256]  Ks[d*256+kv]
    float* Vs = Ks + 64 * 256;       // [256][64]  Vs[kv*64+d]
    float* S  = Vs + 256 * 64;       // [64][SPAD]

    const int tid = threadIdx.x;
    const int bh  = blockIdx.y;
    const int b   = bh >> 3, h = bh & 7;
    const int q0  = blockIdx.x * 64;
    const size_t qbase  = ((size_t)(b * NQ + q0)) * CC + h * DH;
    const size_t kvbase = ((size_t)(b * NKV)) * CC + h * DH;

    // Load Q transposed (d-major)
    for (int i = tid; i < 64 * 16; i += 256) {
        const int qq = i & 63, d4 = (i >> 6) << 2;
        float4 v = *(const float4*)&g_q[qbase + (size_t)qq * CC + d4];
        Qs[(d4 + 0) * 64 + qq] = v.x;
        Qs[(d4 + 1) * 64 + qq] = v.y;
        Qs[(d4 + 2) * 64 + qq] = v.z;
        Qs[(d4 + 3) * 64 + qq] = v.w;
    }
    // Load K transposed (d-major)
    for (int i = tid; i < 256 * 16; i += 256) {
        const int kv = i & 255, d4 = (i >> 8) << 2;
        float4 v = *(const float4*)&g_k[kvbase + (size_t)kv * CC + d4];
        Ks[(d4 + 0) * 256 + kv] = v.x;
        Ks[(d4 + 1) * 256 + kv] = v.y;
        Ks[(d4 + 2) * 256 + kv] = v.z;
        Ks[(d4 + 3) * 256 + kv] = v.w;
    }
    // Load V natural
    for (int i = tid; i < 256 * 16; i += 256) {
        const int kv = i >> 4, d4 = (i & 15) << 2;
        *(float4*)&Vs[kv * 64 + d4] =
            *(const float4*)&g_v[kvbase + (size_t)kv * CC + d4];
    }
    __syncthreads();

    // S = (Q K^T) * scale ; thread -> 8 q-rows x 8 kv-cols
    {
        const int qi = (tid >> 5) << 3;
        const int kj = (tid & 31) << 3;
        float acc[8][8];
#pragma unroll
        for (int i = 0; i < 8; ++i)
#pragma unroll
            for (int j = 0; j < 8; ++j) acc[i][j] = 0.f;

        for (int d = 0; d < 64; ++d) {
            float af[8], bf[8];
            *(float4*)&af[0] = *(const float4*)&Qs[d * 64 + qi];
            *(float4*)&af[4] = *(const float4*)&Qs[d * 64 + qi + 4];
            *(float4*)&bf[0] = *(const float4*)&Ks[d * 256 + kj];
            *(float4*)&bf[4] = *(const float4*)&Ks[d * 256 + kj + 4];
#pragma unroll
            for (int i = 0; i < 8; ++i)
#pragma unroll
                for (int j = 0; j < 8; ++j)
                    acc[i][j] += af[i] * bf[j];
        }
        const float scale = 0.125f;  // 64^-0.5
#pragma unroll
        for (int i = 0; i < 8; ++i)
#pragma unroll
            for (int j = 0; j < 8; j += 4)
                *(float4*)&S[(qi + i) * SPAD + kj + j] =
                    make_float4(acc[i][j] * scale, acc[i][j + 1] * scale,
                                acc[i][j + 2] * scale, acc[i][j + 3] * scale);
    }
    __syncthreads();

    // softmax rows (8 rows per warp)
    {
        const int warp = tid >> 5, lane = tid & 31;
        for (int r = warp; r < 64; r += 8) {
            float* row = &S[r * SPAD];
            float m = -1e30f;
#pragma unroll
            for (int j = 0; j < 8; ++j) m = fmaxf(m, row[lane + j * 32]);
#pragma unroll
            for (int o = 16; o > 0; o >>= 1) m = fmaxf(m, __shfl_xor_sync(0xffffffffu, m, o));
            float s = 0.f;
#pragma unroll
            for (int j = 0; j < 8; ++j) {
                float e = __expf(row[lane + j * 32] - m);
                row[lane + j * 32] = e;
                s += e;
            }
#pragma unroll
            for (int o = 16; o > 0; o >>= 1) s += __shfl_xor_sync(0xffffffffu, s, o);
            const float inv = 1.f / s;
#pragma unroll
            for (int j = 0; j < 8; ++j) row[lane + j * 32] *= inv;
        }
    }
    __syncthreads();

    // O = P @ V ; thread -> 4 q-rows x 4 d-cols
    {
        const int tq = (tid >> 4) << 2;
        const int td = (tid & 15) << 2;
        float o[4][4];
#pragma unroll
        for (int i = 0; i < 4; ++i)
#pragma unroll
            for (int j = 0; j < 4; ++j) o[i][j] = 0.f;

        for (int kv = 0; kv < 256; ++kv) {
            const float p0 = S[(tq + 0) * SPAD + kv];
            const float p1 = S[(tq + 1) * SPAD + kv];
            const float p2 = S[(tq + 2) * SPAD + kv];
            const float p3 = S[(tq + 3) * SPAD + kv];
            const float4 vv = *(const float4*)&Vs[kv * 64 + td];
            o[0][0] += p0 * vv.x; o[0][1] += p0 * vv.y; o[0][2] += p0 * vv.z; o[0][3] += p0 * vv.w;
            o[1][0] += p1 * vv.x; o[1][1] += p1 * vv.y; o[1][2] += p1 * vv.z; o[1][3] += p1 * vv.w;
            o[2][0] += p2 * vv.x; o[2][1] += p2 * vv.y; o[2][2] += p2 * vv.z; o[2][3] += p2 * vv.w;
            o[3][0] += p3 * vv.x; o[3][1] += p3 * vv.y; o[3][2] += p3 * vv.z; o[3][3] += p3 * vv.w;
        }
#pragma unroll
        for (int i = 0; i < 4; ++i)
            *(float4*)&g_attn[qbase + (size_t)(tq + i) * CC + td] =
                make_float4(o[i][0], o[i][1], o[i][2], o[i][3]);
    }
}

// ---------------------------------------------------------------------------
extern "C" void kernel_launch(void* const* d_in, const int* in_sizes, int n_in,
                              void* d_out, int out_size)
{
    (void)in_sizes; (void)n_in; (void)out_size;
    const float* x     = (const float*)d_in[0];
    const float* wq    = (const float*)d_in[1];
    const float* bq    = (const float*)d_in[2];
    const float* wk    = (const float*)d_in[3];
    const float* bk    = (const float*)d_in[4];
    const float* wv    = (const float*)d_in[5];
    const float* bv    = (const float*)d_in[6];
    const float* w_sr  = (const float*)d_in[7];
    const float* b_sr  = (const float*)d_in[8];
    const float* gamma = (const float*)d_in[9];
    const float* beta  = (const float*)d_in[10];
    const float* wp    = (const float*)d_in[11];
    const float* bp    = (const float*)d_in[12];
    float* out = (float*)d_out;

    cudaFuncSetAttribute(attn_kernel, cudaFuncAttributeMaxDynamicSharedMemorySize, ATT_SMEM);

    // Q projection
    qproj_kernel<<<dim3(4, 128), 256>>>(x, wq, bq);
    // Spatial-reduction conv as split-K patch GEMM
    conv_gemm_kernel<<<dim3(4, 8, KSPLIT), 256>>>(x, w_sr);
    // partial reduce + bias + LayerNorm
    ln_kernel<<<dim3(BB * NKV), 128>>>(b_sr, gamma, beta);
    // K and V projections (fused launch)
    kv_gemm_kernel<<<dim3(8, 8), 256>>>(wk, bk, wv, bv);
    // attention
    attn_kernel<<<dim3(NQ / 64, BB * HEADS), 256, ATT_SMEM>>>();
    // output projection
    outproj_kernel<<<dim3(4, 128), 256>>>(wp, bp, out);
}

// round 2
// speedup vs baseline: 2.3874x; 2.3874x over previous
#include <cuda_runtime.h>
#include <math.h>
#include <stdint.h>

#define BB    4
#define NQ    4096
#define CC    512
#define HEADS 8
#define DH    64
#define NKV   256
#define KSPLIT 4
#define KCONV 8192

// ---------------------------------------------------------------------------
// Scratch
// ---------------------------------------------------------------------------
__device__ float g_q[BB * NQ * CC];
__device__ float g_xr_part[KSPLIT * BB * NKV * CC];
__device__ float g_xr[BB * NKV * CC];
__device__ float g_k[BB * NKV * CC];
__device__ float g_v[BB * NKV * CC];
__device__ float g_attn[BB * NQ * CC];

// ---------------------------------------------------------------------------
// tf32 helpers
// ---------------------------------------------------------------------------
__device__ __forceinline__ uint32_t f2tf(float f) {
    uint32_t u;
    asm("cvt.rna.tf32.f32 %0, %1;" : "=r"(u) : "f"(f));
    return u;
}

__device__ __forceinline__ void mma_tf32(float* c,
    uint32_t a0, uint32_t a1, uint32_t a2, uint32_t a3,
    uint32_t b0, uint32_t b1)
{
    asm volatile(
        "mma.sync.aligned.m16n8k8.row.col.f32.tf32.tf32.f32 "
        "{%0,%1,%2,%3},{%4,%5,%6,%7},{%8,%9},{%0,%1,%2,%3};"
        : "+f"(c[0]), "+f"(c[1]), "+f"(c[2]), "+f"(c[3])
        : "r"(a0), "r"(a1), "r"(a2), "r"(a3), "r"(b0), "r"(b1));
}

// ---------------------------------------------------------------------------
// Generic 128x128 tf32 GEMM tile, K-step 16, double buffered.
// 256 threads = 8 warps; warp grid 2(m)x4(n): warp tile 64x32.
// N fixed at 512.
// ---------------------------------------------------------------------------
#define APAD 20
#define BPAD 136

__device__ __forceinline__ void gemm128_tf32(
    const float* __restrict__ A, const float* __restrict__ Bm,
    const float* __restrict__ bias, float* __restrict__ Cm,
    const int K, const int bm, const int bn)
{
    __shared__ uint32_t As[2][128][APAD];
    __shared__ uint32_t Bs[2][16][BPAD];

    const int tid = threadIdx.x;
    const int w = tid >> 5, l = tid & 31;
    const int g = l >> 2, t = l & 3;
    const int wm = (w >> 2) * 64;
    const int wn = (w & 3) * 32;

    const int arow0 = tid >> 2;            // 0..63
    const int arow1 = arow0 + 64;
    const int acol  = (tid & 3) * 4;
    const int brow0 = tid >> 5;            // 0..7
    const int brow1 = brow0 + 8;
    const int bcol  = (tid & 31) * 4;

    float acc[4][4][4];
#pragma unroll
    for (int mi = 0; mi < 4; ++mi)
#pragma unroll
        for (int ni = 0; ni < 4; ++ni)
#pragma unroll
            for (int e = 0; e < 4; ++e) acc[mi][ni][e] = 0.f;

    float4 aR0, aR1, bR0, bR1;

#define LDG_TILE(k0) { \
    aR0 = *(const float4*)&A[(size_t)(bm + arow0) * K + (k0) + acol]; \
    aR1 = *(const float4*)&A[(size_t)(bm + arow1) * K + (k0) + acol]; \
    bR0 = *(const float4*)&Bm[(size_t)((k0) + brow0) * 512 + bn + bcol]; \
    bR1 = *(const float4*)&Bm[(size_t)((k0) + brow1) * 512 + bn + bcol]; }

#define STS_TILE(buf) { \
    As[buf][arow0][acol + 0] = f2tf(aR0.x); As[buf][arow0][acol + 1] = f2tf(aR0.y); \
    As[buf][arow0][acol + 2] = f2tf(aR0.z); As[buf][arow0][acol + 3] = f2tf(aR0.w); \
    As[buf][arow1][acol + 0] = f2tf(aR1.x); As[buf][arow1][acol + 1] = f2tf(aR1.y); \
    As[buf][arow1][acol + 2] = f2tf(aR1.z); As[buf][arow1][acol + 3] = f2tf(aR1.w); \
    Bs[buf][brow0][bcol + 0] = f2tf(bR0.x); Bs[buf][brow0][bcol + 1] = f2tf(bR0.y); \
    Bs[buf][brow0][bcol + 2] = f2tf(bR0.z); Bs[buf][brow0][bcol + 3] = f2tf(bR0.w); \
    Bs[buf][brow1][bcol + 0] = f2tf(bR1.x); Bs[buf][brow1][bcol + 1] = f2tf(bR1.y); \
    Bs[buf][brow1][bcol + 2] = f2tf(bR1.z); Bs[buf][brow1][bcol + 3] = f2tf(bR1.w); }

    LDG_TILE(0);
    STS_TILE(0);
    __syncthreads();

    const int nk = K >> 4;
    for (int kt = 0; kt < nk; ++kt) {
        const int buf = kt & 1;
        const bool nxt = (kt + 1) < nk;
        if (nxt) LDG_TILE((kt + 1) << 4);

#pragma unroll
        for (int kk = 0; kk < 2; ++kk) {
            uint32_t af[4][4], bf[4][2];
#pragma unroll
            for (int mi = 0; mi < 4; ++mi) {
                const int r = wm + mi * 16;
                af[mi][0] = As[buf][r + g][kk * 8 + t];
                af[mi][1] = As[buf][r + g + 8][kk * 8 + t];
                af[mi][2] = As[buf][r + g][kk * 8 + t + 4];
                af[mi][3] = As[buf][r + g + 8][kk * 8 + t + 4];
            }
#pragma unroll
            for (int ni = 0; ni < 4; ++ni) {
                const int n = wn + ni * 8 + g;
                bf[ni][0] = Bs[buf][kk * 8 + t][n];
                bf[ni][1] = Bs[buf][kk * 8 + t + 4][n];
            }
#pragma unroll
            for (int mi = 0; mi < 4; ++mi)
#pragma unroll
                for (int ni = 0; ni < 4; ++ni)
                    mma_tf32(acc[mi][ni], af[mi][0], af[mi][1], af[mi][2], af[mi][3],
                             bf[ni][0], bf[ni][1]);
        }
        if (nxt) STS_TILE(buf ^ 1);
        __syncthreads();
    }
#undef LDG_TILE
#undef STS_TILE

#pragma unroll
    for (int mi = 0; mi < 4; ++mi) {
        const int r = bm + wm + mi * 16 + g;
#pragma unroll
        for (int ni = 0; ni < 4; ++ni) {
            const int cn = bn + wn + ni * 8 + 2 * t;
            float2 v0 = make_float2(acc[mi][ni][0] + bias[cn],
                                    acc[mi][ni][1] + bias[cn + 1]);
            float2 v1 = make_float2(acc[mi][ni][2] + bias[cn],
                                    acc[mi][ni][3] + bias[cn + 1]);
            *(float2*)&Cm[(size_t)r * 512 + cn] = v0;
            *(float2*)&Cm[(size_t)(r + 8) * 512 + cn] = v1;
        }
    }
}

__global__ void qproj_kernel(const float* __restrict__ x,
                             const float* __restrict__ wq,
                             const float* __restrict__ bq)
{
    gemm128_tf32(x, wq, bq, g_q, CC, blockIdx.y * 128, blockIdx.x * 128);
}

__global__ void kv_gemm_kernel(const float* __restrict__ wk,
                               const float* __restrict__ bk,
                               const float* __restrict__ wv,
                               const float* __restrict__ bv)
{
    const int sel = blockIdx.x >> 2;
    const int bn  = (blockIdx.x & 3) * 128;
    gemm128_tf32(g_xr, sel ? wv : wk, sel ? bv : bk, sel ? g_v : g_k,
                 CC, blockIdx.y * 128, bn);
}

__global__ void outproj_kernel(const float* __restrict__ wp,
                               const float* __restrict__ bp,
                               float* __restrict__ out)
{
    gemm128_tf32(g_attn, wp, bp, out, CC, blockIdx.y * 128, blockIdx.x * 128);
}

// ---------------------------------------------------------------------------
// Conv as split-K patch GEMM (tf32). grid(4, 8, KSPLIT)
// ---------------------------------------------------------------------------
__global__ void conv_gemm_kernel(const float* __restrict__ x,
                                 const float* __restrict__ w_sr)
{
    __shared__ uint32_t As[2][128][APAD];
    __shared__ uint32_t Bs[2][16][BPAD];

    const int tid   = threadIdx.x;
    const int w = tid >> 5, l = tid & 31;
    const int g = l >> 2, t = l & 3;
    const int wm = (w >> 2) * 64;
    const int wn = (w & 3) * 32;

    const int bm    = blockIdx.y * 128;
    const int bn    = blockIdx.x * 128;
    const int kbase = blockIdx.z * (KCONV / KSPLIT);
    float* Cm = g_xr_part + (size_t)blockIdx.z * (BB * NKV * CC);

    const int arow0 = tid >> 2;
    const int arow1 = arow0 + 64;
    const int acol  = (tid & 3) * 4;
    const int brow0 = tid >> 5;
    const int brow1 = brow0 + 8;
    const int bcol  = (tid & 31) * 4;

    // precompute top-left pixel index of each A row's patch
    const int r0g = bm + arow0;
    const int r1g = bm + arow1;
    const int pix0 = (r0g >> 8) * 4096 + (((r0g >> 4) & 15) * 4) * 64 + (r0g & 15) * 4;
    const int pix1 = (r1g >> 8) * 4096 + (((r1g >> 4) & 15) * 4) * 64 + (r1g & 15) * 4;

    float acc[4][4][4];
#pragma unroll
    for (int mi = 0; mi < 4; ++mi)
#pragma unroll
        for (int ni = 0; ni < 4; ++ni)
#pragma unroll
            for (int e = 0; e < 4; ++e) acc[mi][ni][e] = 0.f;

    float4 aR0, aR1, bR0, bR1;

#define LDG_C(k0) { \
    const int kidx = kbase + (k0) + acol; \
    const int kh = kidx >> 11, kw = (kidx >> 9) & 3, ci = kidx & 511; \
    aR0 = *(const float4*)&x[(size_t)(pix0 + kh * 64 + kw) * 512 + ci]; \
    aR1 = *(const float4*)&x[(size_t)(pix1 + kh * 64 + kw) * 512 + ci]; \
    bR0 = *(const float4*)&w_sr[(size_t)(kbase + (k0) + brow0) * 512 + bn + bcol]; \
    bR1 = *(const float4*)&w_sr[(size_t)(kbase + (k0) + brow1) * 512 + bn + bcol]; }

#define STS_C(buf) { \
    As[buf][arow0][acol + 0] = f2tf(aR0.x); As[buf][arow0][acol + 1] = f2tf(aR0.y); \
    As[buf][arow0][acol + 2] = f2tf(aR0.z); As[buf][arow0][acol + 3] = f2tf(aR0.w); \
    As[buf][arow1][acol + 0] = f2tf(aR1.x); As[buf][arow1][acol + 1] = f2tf(aR1.y); \
    As[buf][arow1][acol + 2] = f2tf(aR1.z); As[buf][arow1][acol + 3] = f2tf(aR1.w); \
    Bs[buf][brow0][bcol + 0] = f2tf(bR0.x); Bs[buf][brow0][bcol + 1] = f2tf(bR0.y); \
    Bs[buf][brow0][bcol + 2] = f2tf(bR0.z); Bs[buf][brow0][bcol + 3] = f2tf(bR0.w); \
    Bs[buf][brow1][bcol + 0] = f2tf(bR1.x); Bs[buf][brow1][bcol + 1] = f2tf(bR1.y); \
    Bs[buf][brow1][bcol + 2] = f2tf(bR1.z); Bs[buf][brow1][bcol + 3] = f2tf(bR1.w); }

    LDG_C(0);
    STS_C(0);
    __syncthreads();

    const int nk = (KCONV / KSPLIT) >> 4;   // 128
    for (int kt = 0; kt < nk; ++kt) {
        const int buf = kt & 1;
        const bool nxt = (kt + 1) < nk;
        if (nxt) LDG_C((kt + 1) << 4);

#pragma unroll
        for (int kk = 0; kk < 2; ++kk) {
            uint32_t af[4][4], bf[4][2];
#pragma unroll
            for (int mi = 0; mi < 4; ++mi) {
                const int r = wm + mi * 16;
                af[mi][0] = As[buf][r + g][kk * 8 + t];
                af[mi][1] = As[buf][r + g + 8][kk * 8 + t];
                af[mi][2] = As[buf][r + g][kk * 8 + t + 4];
                af[mi][3] = As[buf][r + g + 8][kk * 8 + t + 4];
            }
#pragma unroll
            for (int ni = 0; ni < 4; ++ni) {
                const int n = wn + ni * 8 + g;
                bf[ni][0] = Bs[buf][kk * 8 + t][n];
                bf[ni][1] = Bs[buf][kk * 8 + t + 4][n];
            }
#pragma unroll
            for (int mi = 0; mi < 4; ++mi)
#pragma unroll
                for (int ni = 0; ni < 4; ++ni)
                    mma_tf32(acc[mi][ni], af[mi][0], af[mi][1], af[mi][2], af[mi][3],
                             bf[ni][0], bf[ni][1]);
        }
        if (nxt) STS_C(buf ^ 1);
        __syncthreads();
    }
#undef LDG_C
#undef STS_C

#pragma unroll
    for (int mi = 0; mi < 4; ++mi) {
        const int r = bm + wm + mi * 16 + g;
#pragma unroll
        for (int ni = 0; ni < 4; ++ni) {
            const int cn = bn + wn + ni * 8 + 2 * t;
            *(float2*)&Cm[(size_t)r * 512 + cn] =
                make_float2(acc[mi][ni][0], acc[mi][ni][1]);
            *(float2*)&Cm[(size_t)(r + 8) * 512 + cn] =
                make_float2(acc[mi][ni][2], acc[mi][ni][3]);
        }
    }
}

// ---------------------------------------------------------------------------
// split-K reduce + bias + LayerNorm
// ---------------------------------------------------------------------------
__global__ void ln_kernel(const float* __restrict__ bsr,
                          const float* __restrict__ gamma,
                          const float* __restrict__ beta)
{
    const int r   = blockIdx.x;
    const int tid = threadIdx.x;

    float v[4];
    float s1 = 0.f, s2 = 0.f;
#pragma unroll
    for (int i = 0; i < 4; ++i) {
        const int c = tid + i * 128;
        const size_t off = (size_t)r * 512 + c;
        float tt = g_xr_part[off]
                 + g_xr_part[(size_t)1 * BB * NKV * CC + off]
                 + g_xr_part[(size_t)2 * BB * NKV * CC + off]
                 + g_xr_part[(size_t)3 * BB * NKV * CC + off]
                 + bsr[c];
        v[i] = tt;
        s1 += tt;
        s2 += tt * tt;
    }
#pragma unroll
    for (int o = 16; o > 0; o >>= 1) {
        s1 += __shfl_xor_sync(0xffffffffu, s1, o);
        s2 += __shfl_xor_sync(0xffffffffu, s2, o);
    }
    __shared__ float red[8];
    const int warp = tid >> 5, lane = tid & 31;
    if (lane == 0) { red[warp] = s1; red[warp + 4] = s2; }
    __syncthreads();
    s1 = red[0] + red[1] + red[2] + red[3];
    s2 = red[4] + red[5] + red[6] + red[7];

    const float mu   = s1 * (1.f / 512.f);
    const float var  = s2 * (1.f / 512.f) - mu * mu;
    const float rstd = rsqrtf(var + 1e-5f);

#pragma unroll
    for (int i = 0; i < 4; ++i) {
        const int c = tid + i * 128;
        g_xr[(size_t)r * 512 + c] = (v[i] - mu) * rstd * gamma[c] + beta[c];
    }
}

// ---------------------------------------------------------------------------
// Attention with tf32 mma: CTA = 64 q-rows x full 256 kv for one (b,h).
// smem: [Q | K] union [V], plus S. 8 warps.
// ---------------------------------------------------------------------------
#define QPAD  68
#define KPAD  264
#define VPAD  72
#define SPAD2 268
#define UNION_FLOATS (64 * QPAD + 64 * KPAD)   // 21248 >= 256*VPAD (18432)
#define ATT_SMEM ((UNION_FLOATS + 64 * SPAD2) * 4)

__global__ void attn_kernel()
{
    extern __shared__ float sm[];
    uint32_t* Qs = (uint32_t*)sm;                       // [64][QPAD]
    uint32_t* Ks = (uint32_t*)(sm + 64 * QPAD);         // [64][KPAD]  (d-major)
    uint32_t* Vs = (uint32_t*)sm;                       // [256][VPAD] aliases Q/K
    float*    S  = sm + UNION_FLOATS;                   // [64][SPAD2]

    const int tid = threadIdx.x;
    const int w = tid >> 5, l = tid & 31;
    const int g = l >> 2, t = l & 3;

    const int bh = blockIdx.y;
    const int b = bh >> 3, h = bh & 7;
    const int q0 = blockIdx.x * 64;
    const size_t qbase  = ((size_t)(b * NQ + q0)) * CC + h * DH;
    const size_t kvbase = ((size_t)(b * NKV)) * CC + h * DH;

    // ---- load Q [64][64] (natural, tf32) ----
    for (int c = tid; c < 64 * 16; c += 256) {
        const int row = c >> 4, col = (c & 15) * 4;
        float4 v = *(const float4*)&g_q[qbase + (size_t)row * CC + col];
        uint32_t* p = &Qs[row * QPAD + col];
        p[0] = f2tf(v.x); p[1] = f2tf(v.y); p[2] = f2tf(v.z); p[3] = f2tf(v.w);
    }
    // ---- load K transposed: Ks[d][kv] ----
    {
        const int kv = tid;  // 256 threads = 256 kv rows
#pragma unroll
        for (int j = 0; j < 16; ++j) {
            const int d4 = j * 4;
            float4 v = *(const float4*)&g_k[kvbase + (size_t)kv * CC + d4];
            Ks[(d4 + 0) * KPAD + kv] = f2tf(v.x);
            Ks[(d4 + 1) * KPAD + kv] = f2tf(v.y);
            Ks[(d4 + 2) * KPAD + kv] = f2tf(v.z);
            Ks[(d4 + 3) * KPAD + kv] = f2tf(v.w);
        }
    }
    __syncthreads();

    // ---- S = Q K^T * scale : warp grid 4(m) x 2(n) ----
    {
        const int wm = (w >> 1) * 16;
        const int wn = (w & 1) * 128;
        float accS[16][4];
#pragma unroll
        for (int ni = 0; ni < 16; ++ni)
#pragma unroll
            for (int e = 0; e < 4; ++e) accS[ni][e] = 0.f;

#pragma unroll
        for (int kk = 0; kk < 8; ++kk) {
            const uint32_t a0 = Qs[(wm + g) * QPAD + kk * 8 + t];
            const uint32_t a1 = Qs[(wm + g + 8) * QPAD + kk * 8 + t];
            const uint32_t a2 = Qs[(wm + g) * QPAD + kk * 8 + t + 4];
            const uint32_t a3 = Qs[(wm + g + 8) * QPAD + kk * 8 + t + 4];
#pragma unroll
            for (int ni = 0; ni < 16; ++ni) {
                const int n = wn + ni * 8 + g;
                const uint32_t b0 = Ks[(kk * 8 + t) * KPAD + n];
                const uint32_t b1 = Ks[(kk * 8 + t + 4) * KPAD + n];
                mma_tf32(accS[ni], a0, a1, a2, a3, b0, b1);
            }
        }
        const float scale = 0.125f;
#pragma unroll
        for (int ni = 0; ni < 16; ++ni) {
            const int cn = wn + ni * 8 + 2 * t;
            S[(wm + g) * SPAD2 + cn]         = accS[ni][0] * scale;
            S[(wm + g) * SPAD2 + cn + 1]     = accS[ni][1] * scale;
            S[(wm + g + 8) * SPAD2 + cn]     = accS[ni][2] * scale;
            S[(wm + g + 8) * SPAD2 + cn + 1] = accS[ni][3] * scale;
        }
    }
    __syncthreads();

    // ---- load V (aliases Q/K region) + softmax on S ----
    for (int c = tid; c < 256 * 16; c += 256) {
        const int kv = c >> 4, d4 = (c & 15) * 4;
        float4 v = *(const float4*)&g_v[kvbase + (size_t)kv * CC + d4];
        uint32_t* p = &Vs[kv * VPAD + d4];
        p[0] = f2tf(v.x); p[1] = f2tf(v.y); p[2] = f2tf(v.z); p[3] = f2tf(v.w);
    }
    {
        for (int r = w; r < 64; r += 8) {
            float* row = &S[r * SPAD2];
            float m = -1e30f;
#pragma unroll
            for (int j = 0; j < 8; ++j) m = fmaxf(m, row[l + j * 32]);
#pragma unroll
            for (int o = 16; o > 0; o >>= 1) m = fmaxf(m, __shfl_xor_sync(0xffffffffu, m, o));
            float s = 0.f;
#pragma unroll
            for (int j = 0; j < 8; ++j) {
                float e = __expf(row[l + j * 32] - m);
                row[l + j * 32] = e;
                s += e;
            }
#pragma unroll
            for (int o = 16; o > 0; o >>= 1) s += __shfl_xor_sync(0xffffffffu, s, o);
            const float inv = 1.f / s;
#pragma unroll
            for (int j = 0; j < 8; ++j) row[l + j * 32] *= inv;
        }
    }
    __syncthreads();

    // ---- O = P @ V : warp grid 4(m) x 2(n), warp tile 16x32 ----
    {
        const int wm = (w >> 1) * 16;
        const int wn = (w & 1) * 32;
        float accO[4][4];
#pragma unroll
        for (int ni = 0; ni < 4; ++ni)
#pragma unroll
            for (int e = 0; e < 4; ++e) accO[ni][e] = 0.f;

        for (int kk = 0; kk < 32; ++kk) {
            const uint32_t a0 = f2tf(S[(wm + g) * SPAD2 + kk * 8 + t]);
            const uint32_t a1 = f2tf(S[(wm + g + 8) * SPAD2 + kk * 8 + t]);
            const uint32_t a2 = f2tf(S[(wm + g) * SPAD2 + kk * 8 + t + 4]);
            const uint32_t a3 = f2tf(S[(wm + g + 8) * SPAD2 + kk * 8 + t + 4]);
#pragma unroll
            for (int ni = 0; ni < 4; ++ni) {
                const int n = wn + ni * 8 + g;
                const uint32_t b0 = Vs[(kk * 8 + t) * VPAD + n];
                const uint32_t b1 = Vs[(kk * 8 + t + 4) * VPAD + n];
                mma_tf32(accO[ni], a0, a1, a2, a3, b0, b1);
            }
        }
#pragma unroll
        for (int ni = 0; ni < 4; ++ni) {
            const int cn = wn + ni * 8 + 2 * t;
            *(float2*)&g_attn[qbase + (size_t)(wm + g) * CC + cn] =
                make_float2(accO[ni][0], accO[ni][1]);
            *(float2*)&g_attn[qbase + (size_t)(wm + g + 8) * CC + cn] =
                make_float2(accO[ni][2], accO[ni][3]);
        }
    }
}

// ---------------------------------------------------------------------------
extern "C" void kernel_launch(void* const* d_in, const int* in_sizes, int n_in,
                              void* d_out, int out_size)
{
    (void)in_sizes; (void)n_in; (void)out_size;
    const float* x     = (const float*)d_in[0];
    const float* wq    = (const float*)d_in[1];
    const float* bq    = (const float*)d_in[2];
    const float* wk    = (const float*)d_in[3];
    const float* bk    = (const float*)d_in[4];
    const float* wv    = (const float*)d_in[5];
    const float* bv    = (const float*)d_in[6];
    const float* w_sr  = (const float*)d_in[7];
    const float* b_sr  = (const float*)d_in[8];
    const float* gamma = (const float*)d_in[9];
    const float* beta  = (const float*)d_in[10];
    const float* wp    = (const float*)d_in[11];
    const float* bp    = (const float*)d_in[12];
    float* out = (float*)d_out;

    cudaFuncSetAttribute(attn_kernel, cudaFuncAttributeMaxDynamicSharedMemorySize, ATT_SMEM);

    qproj_kernel<<<dim3(4, 128), 256>>>(x, wq, bq);
    conv_gemm_kernel<<<dim3(4, 8, KSPLIT), 256>>>(x, w_sr);
    ln_kernel<<<dim3(BB * NKV), 128>>>(b_sr, gamma, beta);
    kv_gemm_kernel<<<dim3(8, 8), 256>>>(wk, bk, wv, bv);
    attn_kernel<<<dim3(NQ / 64, BB * HEADS), 256, ATT_SMEM>>>();
    outproj_kernel<<<dim3(4, 128), 256>>>(wp, bp, out);
}

// round 4
// speedup vs baseline: 3.5152x; 1.4724x over previous
#include <cuda_runtime.h>
#include <cuda_fp16.h>
#include <math.h>
#include <stdint.h>

#define BB    4
#define NQ    4096
#define CC    512
#define HEADS 8
#define DH    64
#define NKV   256
#define KCONV 8192
#define CSPLIT 16

// ---------------------------------------------------------------------------
// Scratch
// ---------------------------------------------------------------------------
__device__ __half g_qh[BB * NQ * CC];
__device__ __half g_kh[BB * NKV * CC];
__device__ __half g_vh[BB * NKV * CC];
__device__ __half g_attnh[BB * NQ * CC];
__device__ float  g_xr[BB * NKV * CC];
__device__ float  g_xr_part[CSPLIT * BB * NKV * CC];
__device__ __half g_wqt[CC * CC];
__device__ __half g_wkt[CC * CC];
__device__ __half g_wvt[CC * CC];
__device__ __half g_wpt[CC * CC];
__device__ __half g_wsrt[(size_t)CC * KCONV];

// ---------------------------------------------------------------------------
// fp16 mma helpers
// ---------------------------------------------------------------------------
__device__ __forceinline__ void mma_f16(float* c,
    uint32_t a0, uint32_t a1, uint32_t a2, uint32_t a3, uint32_t b0, uint32_t b1)
{
    asm volatile(
        "mma.sync.aligned.m16n8k16.row.col.f32.f16.f16.f32 "
        "{%0,%1,%2,%3},{%4,%5,%6,%7},{%8,%9},{%0,%1,%2,%3};"
        : "+f"(c[0]), "+f"(c[1]), "+f"(c[2]), "+f"(c[3])
        : "r"(a0), "r"(a1), "r"(a2), "r"(a3), "r"(b0), "r"(b1));
}

__device__ __forceinline__ uint4 pack8(float4 u, float4 v) {
    __half2 h0 = __floats2half2_rn(u.x, u.y);
    __half2 h1 = __floats2half2_rn(u.z, u.w);
    __half2 h2 = __floats2half2_rn(v.x, v.y);
    __half2 h3 = __floats2half2_rn(v.z, v.w);
    uint4 r;
    r.x = *(uint32_t*)&h0; r.y = *(uint32_t*)&h1;
    r.z = *(uint32_t*)&h2; r.w = *(uint32_t*)&h3;
    return r;
}

// ---------------------------------------------------------------------------
// fp16 mma.sync GEMM: 128x128 tile, K-step 32, double buffered.
// 256 threads = 8 warps; warp grid 2(m) x 4(n): warp tile 64x32.
// A row-major (f32 / f16 / conv-gather f32), B pre-transposed fp16 [N][K].
// AMODE: 0 = f32 A, 1 = half A, 2 = conv patch gather f32.
// ---------------------------------------------------------------------------
#define KP40 40

template<int AMODE, bool OUTHALF, bool BIAS>
__device__ __forceinline__ void gemm_f16_body(
    const void* __restrict__ Ap, long lda,
    const __half* __restrict__ Bt, long ldb, int kb,
    const float* __restrict__ bias,
    void* __restrict__ Cp, long ldc,
    int nkt, int bm, int bn, int convoff)
{
    __shared__ __half As[2][128][KP40];
    __shared__ __half Bs[2][128][KP40];
    __shared__ float sbias[128];

    const int tid = threadIdx.x;
    const int w = tid >> 5, l = tid & 31;
    const int g = l >> 2, t = l & 3;
    const int wm = (w >> 2) * 64;
    const int wn = (w & 3) * 32;

    if (BIAS && tid < 128) sbias[tid] = bias[bn + tid];

    const int r  = tid >> 1;           // 0..127
    const int sg = (tid & 1) * 16;     // 0 or 16

    // gmem row base for A
    const float* arow_f = nullptr;
    const __half* arow_h = nullptr;
    if (AMODE == 1) {
        arow_h = (const __half*)Ap + (size_t)(bm + r) * lda;
    } else if (AMODE == 2) {
        const int gr = bm + r;
        const int pix = (gr >> 8) * 4096 + (((gr >> 4) & 15) << 8) + ((gr & 15) << 2);
        arow_f = (const float*)Ap + (size_t)(pix + convoff) * 512;
    } else {
        arow_f = (const float*)Ap + (size_t)(bm + r) * lda;
    }
    const __half* brow = Bt + (size_t)(bn + r) * ldb + kb;

    float acc[4][4][4];
#pragma unroll
    for (int mi = 0; mi < 4; ++mi)
#pragma unroll
        for (int ni = 0; ni < 4; ++ni)
#pragma unroll
            for (int e = 0; e < 4; ++e) acc[mi][ni][e] = 0.f;

    uint4 aU0, aU1, bU0, bU1;

#define LDG_T(k0) { \
    if (AMODE == 1) { \
        aU0 = *(const uint4*)(arow_h + (k0) + sg); \
        aU1 = *(const uint4*)(arow_h + (k0) + sg + 8); \
    } else { \
        const float* p = arow_f + (k0) + sg; \
        aU0 = pack8(*(const float4*)p, *(const float4*)(p + 4)); \
        aU1 = pack8(*(const float4*)(p + 8), *(const float4*)(p + 12)); \
    } \
    bU0 = *(const uint4*)(brow + (k0) + sg); \
    bU1 = *(const uint4*)(brow + (k0) + sg + 8); }

#define STS_T(buf) { \
    *(uint4*)&As[buf][r][sg]     = aU0; \
    *(uint4*)&As[buf][r][sg + 8] = aU1; \
    *(uint4*)&Bs[buf][r][sg]     = bU0; \
    *(uint4*)&Bs[buf][r][sg + 8] = bU1; }

    LDG_T(0);
    STS_T(0);
    __syncthreads();

    for (int kt = 0; kt < nkt; ++kt) {
        const int buf = kt & 1;
        const bool nxt = (kt + 1) < nkt;
        if (nxt) LDG_T((kt + 1) * 32);

#pragma unroll
        for (int kk = 0; kk < 2; ++kk) {
            const int k16 = kk * 16 + 2 * t;
            uint32_t a[4][4], b[4][2];
#pragma unroll
            for (int mi = 0; mi < 4; ++mi) {
                const int rr = wm + mi * 16 + g;
                a[mi][0] = *(const uint32_t*)&As[buf][rr][k16];
                a[mi][1] = *(const uint32_t*)&As[buf][rr + 8][k16];
                a[mi][2] = *(const uint32_t*)&As[buf][rr][k16 + 8];
                a[mi][3] = *(const uint32_t*)&As[buf][rr + 8][k16 + 8];
            }
#pragma unroll
            for (int ni = 0; ni < 4; ++ni) {
                const int n = wn + ni * 8 + g;
                b[ni][0] = *(const uint32_t*)&Bs[buf][n][k16];
                b[ni][1] = *(const uint32_t*)&Bs[buf][n][k16 + 8];
            }
#pragma unroll
            for (int mi = 0; mi < 4; ++mi)
#pragma unroll
                for (int ni = 0; ni < 4; ++ni)
                    mma_f16(acc[mi][ni], a[mi][0], a[mi][1], a[mi][2], a[mi][3],
                            b[ni][0], b[ni][1]);
        }
        if (nxt) STS_T(buf ^ 1);
        __syncthreads();
    }
#undef LDG_T
#undef STS_T

#pragma unroll
    for (int mi = 0; mi < 4; ++mi) {
        const int r0 = bm + wm + mi * 16 + g;
#pragma unroll
        for (int ni = 0; ni < 4; ++ni) {
            const int cl = wn + ni * 8 + 2 * t;   // local col in [0,128)
            const int cn = bn + cl;
            float f0 = acc[mi][ni][0], f1 = acc[mi][ni][1];
            float f2 = acc[mi][ni][2], f3 = acc[mi][ni][3];
            if (BIAS) {
                const float b0 = sbias[cl], b1 = sbias[cl + 1];
                f0 += b0; f1 += b1; f2 += b0; f3 += b1;
            }
            if (OUTHALF) {
                __half* C = (__half*)Cp;
                *(__half2*)&C[(size_t)r0 * ldc + cn] = __floats2half2_rn(f0, f1);
                *(__half2*)&C[(size_t)(r0 + 8) * ldc + cn] = __floats2half2_rn(f2, f3);
            } else {
                float* C = (float*)Cp;
                *(float2*)&C[(size_t)r0 * ldc + cn] = make_float2(f0, f1);
                *(float2*)&C[(size_t)(r0 + 8) * ldc + cn] = make_float2(f2, f3);
            }
        }
    }
}

__global__ void __launch_bounds__(256) qproj_tc(const float* __restrict__ x,
                                                const float* __restrict__ bq)
{
    gemm_f16_body<0, true, true>(x, 512, g_wqt, 512, 0, bq, g_qh, 512, 16,
                                 blockIdx.y * 128, blockIdx.x * 128, 0);
}
__global__ void __launch_bounds__(256) kv_tc(const float* __restrict__ bk,
                                             const float* __restrict__ bv)
{
    const int sel = blockIdx.x >> 2;
    const int bn = (blockIdx.x & 3) * 128;
    if (sel == 0)
        gemm_f16_body<0, true, true>(g_xr, 512, g_wkt, 512, 0, bk, g_kh, 512, 16,
                                     blockIdx.y * 128, bn, 0);
    else
        gemm_f16_body<0, true, true>(g_xr, 512, g_wvt, 512, 0, bv, g_vh, 512, 16,
                                     blockIdx.y * 128, bn, 0);
}
__global__ void __launch_bounds__(256) outproj_tc(const float* __restrict__ bp,
                                                  float* __restrict__ out)
{
    gemm_f16_body<1, false, true>(g_attnh, 512, g_wpt, 512, 0, bp, out, 512, 16,
                                  blockIdx.y * 128, blockIdx.x * 128, 0);
}
__global__ void __launch_bounds__(256) conv_tc(const float* __restrict__ x)
{
    const int z = blockIdx.z;
    gemm_f16_body<2, false, false>(x, 512, g_wsrt, KCONV, z * 512, nullptr,
                                   g_xr_part + (size_t)z * (BB * NKV * CC), 512, 16,
                                   blockIdx.y * 128, blockIdx.x * 128,
                                   ((z >> 2) << 6) | (z & 3));
}

// ---------------------------------------------------------------------------
// Weight transpose fp32[K][N] -> fp16[N][K]
// ---------------------------------------------------------------------------
__global__ void transpose_h_kernel(const float* __restrict__ src, __half* __restrict__ dst,
                                   int Kd, int Nd)
{
    __shared__ float t[32][33];
    const int n0 = blockIdx.x * 32, k0 = blockIdx.y * 32;
    const int tx = threadIdx.x, ty = threadIdx.y;
#pragma unroll
    for (int i = 0; i < 4; ++i)
        t[ty + i * 8][tx] = src[(size_t)(k0 + ty + i * 8) * Nd + n0 + tx];
    __syncthreads();
#pragma unroll
    for (int i = 0; i < 4; ++i)
        dst[(size_t)(n0 + ty + i * 8) * Kd + k0 + tx] = __float2half(t[tx][ty + i * 8]);
}

// ---------------------------------------------------------------------------
// split-K reduce + bias + LayerNorm (CSPLIT partials)
// ---------------------------------------------------------------------------
__global__ void ln_kernel(const float* __restrict__ bsr,
                          const float* __restrict__ gamma,
                          const float* __restrict__ beta)
{
    const int r = blockIdx.x;
    const int tid = threadIdx.x;
    float v[4];
    float s1 = 0.f, s2 = 0.f;
#pragma unroll
    for (int i = 0; i < 4; ++i) {
        const int c = tid + i * 128;
        const size_t off = (size_t)r * 512 + c;
        float tt = bsr[c];
#pragma unroll
        for (int p = 0; p < CSPLIT; ++p)
            tt += g_xr_part[(size_t)p * (BB * NKV * CC) + off];
        v[i] = tt;
        s1 += tt;
        s2 += tt * tt;
    }
#pragma unroll
    for (int o = 16; o > 0; o >>= 1) {
        s1 += __shfl_xor_sync(0xffffffffu, s1, o);
        s2 += __shfl_xor_sync(0xffffffffu, s2, o);
    }
    __shared__ float red[8];
    const int warp = tid >> 5, lane = tid & 31;
    if (lane == 0) { red[warp] = s1; red[warp + 4] = s2; }
    __syncthreads();
    s1 = red[0] + red[1] + red[2] + red[3];
    s2 = red[4] + red[5] + red[6] + red[7];
    const float mu = s1 * (1.f / 512.f);
    const float var = s2 * (1.f / 512.f) - mu * mu;
    const float rstd = rsqrtf(var + 1e-5f);
#pragma unroll
    for (int i = 0; i < 4; ++i) {
        const int c = tid + i * 128;
        g_xr[(size_t)r * 512 + c] = (v[i] - mu) * rstd * gamma[c] + beta[c];
    }
}

// ---------------------------------------------------------------------------
// Attention, fp16 mma.sync m16n8k16. CTA = 64 q x 256 kv per (b,h).
// ---------------------------------------------------------------------------
#define QP 72
#define KP 72
#define VP 264
#define SP 264
#define PP 272
#define ATT_SMEM ((4608 + 18432 + 16896) * 2 + 16896 * 4)

__global__ void __launch_bounds__(256) attn_kernel()
{
    extern __shared__ __align__(1024) char smem[];
    __half* Qh = (__half*)smem;            // [64][QP]
    __half* Kh = Qh + 4608;                // [256][KP]
    __half* Vh = Qh + 23040;               // [64][VP]  (transposed V: Vh[d][kv])
    float*  S  = (float*)(smem + 79872);   // [64][SP]
    __half* Ph = Qh;                       // aliases Q/K after S computed [64][PP]

    const int tid = threadIdx.x;
    const int w = tid >> 5, l = tid & 31;
    const int g = l >> 2, t = l & 3;

    const int bh = blockIdx.y;
    const int b = bh >> 3, h = bh & 7;
    const int q0 = blockIdx.x * 64;
    const size_t qbase  = ((size_t)(b * NQ + q0)) * CC + h * DH;
    const size_t kvbase = ((size_t)(b * NKV)) * CC + h * DH;

    // Q: 64 rows x 64 halves = 512 8-half chunks
#pragma unroll
    for (int i = 0; i < 2; ++i) {
        const int c = tid + i * 256;
        const int r = c >> 3, seg = (c & 7) * 8;
        *(uint4*)&Qh[r * QP + seg] = *(const uint4*)&g_qh[qbase + (size_t)r * CC + seg];
    }
    // K: 2048 chunks
#pragma unroll
    for (int i = 0; i < 8; ++i) {
        const int c = tid + i * 256;
        const int r = c >> 3, seg = (c & 7) * 8;
        *(uint4*)&Kh[r * KP + seg] = *(const uint4*)&g_kh[kvbase + (size_t)r * CC + seg];
    }
    // V transposed: Vh[d][kv]
#pragma unroll
    for (int i = 0; i < 8; ++i) {
        const int c = tid + i * 256;
        const int kv = c >> 3, d0 = (c & 7) * 8;
        uint4 pk = *(const uint4*)&g_vh[kvbase + (size_t)kv * CC + d0];
        const __half* hv = (const __half*)&pk;
#pragma unroll
        for (int j = 0; j < 8; ++j)
            Vh[(d0 + j) * VP + kv] = hv[j];
    }
    __syncthreads();

    // ---- S = Q K^T * scale : warps 2m x 4n, warp tile 32x64 ----
    {
        const int wm = (w >> 2) * 32;
        const int wn = (w & 3) * 64;
        float accS[2][8][4];
#pragma unroll
        for (int mi = 0; mi < 2; ++mi)
#pragma unroll
            for (int ni = 0; ni < 8; ++ni)
#pragma unroll
                for (int e = 0; e < 4; ++e) accS[mi][ni][e] = 0.f;

#pragma unroll
        for (int kk = 0; kk < 4; ++kk) {
            const int k0 = kk * 16;
            uint32_t a[2][4];
#pragma unroll
            for (int mi = 0; mi < 2; ++mi) {
                const int rr = wm + mi * 16 + g;
                a[mi][0] = *(const uint32_t*)&Qh[rr * QP + k0 + 2 * t];
                a[mi][1] = *(const uint32_t*)&Qh[(rr + 8) * QP + k0 + 2 * t];
                a[mi][2] = *(const uint32_t*)&Qh[rr * QP + k0 + 2 * t + 8];
                a[mi][3] = *(const uint32_t*)&Qh[(rr + 8) * QP + k0 + 2 * t + 8];
            }
#pragma unroll
            for (int ni = 0; ni < 8; ++ni) {
                const int n = wn + ni * 8 + g;
                const uint32_t b0 = *(const uint32_t*)&Kh[n * KP + k0 + 2 * t];
                const uint32_t b1 = *(const uint32_t*)&Kh[n * KP + k0 + 2 * t + 8];
#pragma unroll
                for (int mi = 0; mi < 2; ++mi)
                    mma_f16(accS[mi][ni], a[mi][0], a[mi][1], a[mi][2], a[mi][3], b0, b1);
            }
        }
        const float sc = 0.125f;
#pragma unroll
        for (int mi = 0; mi < 2; ++mi) {
            const int rr = wm + mi * 16 + g;
#pragma unroll
            for (int ni = 0; ni < 8; ++ni) {
                const int cn = wn + ni * 8 + 2 * t;
                *(float2*)&S[rr * SP + cn] = make_float2(accS[mi][ni][0] * sc, accS[mi][ni][1] * sc);
                *(float2*)&S[(rr + 8) * SP + cn] = make_float2(accS[mi][ni][2] * sc, accS[mi][ni][3] * sc);
            }
        }
    }
    __syncthreads();

    // ---- softmax rows -> Ph (half), aliases Q/K ----
    for (int r = w; r < 64; r += 8) {
        float* row = &S[r * SP];
        float m = -1e30f;
#pragma unroll
        for (int j = 0; j < 8; ++j) m = fmaxf(m, row[l + j * 32]);
#pragma unroll
        for (int o = 16; o > 0; o >>= 1) m = fmaxf(m, __shfl_xor_sync(0xffffffffu, m, o));
        float s = 0.f;
        float e[8];
#pragma unroll
        for (int j = 0; j < 8; ++j) {
            e[j] = __expf(row[l + j * 32] - m);
            s += e[j];
        }
#pragma unroll
        for (int o = 16; o > 0; o >>= 1) s += __shfl_xor_sync(0xffffffffu, s, o);
        const float inv = 1.f / s;
#pragma unroll
        for (int j = 0; j < 8; ++j)
            Ph[r * PP + l + j * 32] = __float2half(e[j] * inv);
    }
    __syncthreads();

    // ---- O = P @ V : warps 2m x 4n, warp tile 32x16 ----
    {
        const int wm = (w >> 2) * 32;
        const int wn = (w & 3) * 16;
        float accO[2][2][4];
#pragma unroll
        for (int mi = 0; mi < 2; ++mi)
#pragma unroll
            for (int ni = 0; ni < 2; ++ni)
#pragma unroll
                for (int e2 = 0; e2 < 4; ++e2) accO[mi][ni][e2] = 0.f;

#pragma unroll
        for (int kk = 0; kk < 16; ++kk) {
            const int k0 = kk * 16;
            uint32_t a[2][4];
#pragma unroll
            for (int mi = 0; mi < 2; ++mi) {
                const int rr = wm + mi * 16 + g;
                a[mi][0] = *(const uint32_t*)&Ph[rr * PP + k0 + 2 * t];
                a[mi][1] = *(const uint32_t*)&Ph[(rr + 8) * PP + k0 + 2 * t];
                a[mi][2] = *(const uint32_t*)&Ph[rr * PP + k0 + 2 * t + 8];
                a[mi][3] = *(const uint32_t*)&Ph[(rr + 8) * PP + k0 + 2 * t + 8];
            }
#pragma unroll
            for (int ni = 0; ni < 2; ++ni) {
                const int n = wn + ni * 8 + g;
                const uint32_t b0 = *(const uint32_t*)&Vh[n * VP + k0 + 2 * t];
                const uint32_t b1 = *(const uint32_t*)&Vh[n * VP + k0 + 2 * t + 8];
#pragma unroll
                for (int mi = 0; mi < 2; ++mi)
                    mma_f16(accO[mi][ni], a[mi][0], a[mi][1], a[mi][2], a[mi][3], b0, b1);
            }
        }
#pragma unroll
        for (int mi = 0; mi < 2; ++mi) {
            const int rr = wm + mi * 16 + g;
#pragma unroll
            for (int ni = 0; ni < 2; ++ni) {
                const int cn = wn + ni * 8 + 2 * t;
                *(__half2*)&g_attnh[qbase + (size_t)rr * CC + cn] =
                    __floats2half2_rn(accO[mi][ni][0], accO[mi][ni][1]);
                *(__half2*)&g_attnh[qbase + (size_t)(rr + 8) * CC + cn] =
                    __floats2half2_rn(accO[mi][ni][2], accO[mi][ni][3]);
            }
        }
    }
}

// ---------------------------------------------------------------------------
extern "C" void kernel_launch(void* const* d_in, const int* in_sizes, int n_in,
                              void* d_out, int out_size)
{
    (void)in_sizes; (void)n_in; (void)out_size;
    const float* x     = (const float*)d_in[0];
    const float* wq    = (const float*)d_in[1];
    const float* bq    = (const float*)d_in[2];
    const float* wk    = (const float*)d_in[3];
    const float* bk    = (const float*)d_in[4];
    const float* wv    = (const float*)d_in[5];
    const float* bv    = (const float*)d_in[6];
    const float* w_sr  = (const float*)d_in[7];
    const float* b_sr  = (const float*)d_in[8];
    const float* gamma = (const float*)d_in[9];
    const float* beta  = (const float*)d_in[10];
    const float* wp    = (const float*)d_in[11];
    const float* bp    = (const float*)d_in[12];
    float* out = (float*)d_out;

    cudaFuncSetAttribute(attn_kernel, cudaFuncAttributeMaxDynamicSharedMemorySize, ATT_SMEM);

    __half *wqt, *wkt, *wvt, *wpt, *wsrt;
    cudaGetSymbolAddress((void**)&wqt, g_wqt);
    cudaGetSymbolAddress((void**)&wkt, g_wkt);
    cudaGetSymbolAddress((void**)&wvt, g_wvt);
    cudaGetSymbolAddress((void**)&wpt, g_wpt);
    cudaGetSymbolAddress((void**)&wsrt, g_wsrt);

    transpose_h_kernel<<<dim3(16, 16), dim3(32, 8)>>>(wq, wqt, 512, 512);
    transpose_h_kernel<<<dim3(16, 16), dim3(32, 8)>>>(wk, wkt, 512, 512);
    transpose_h_kernel<<<dim3(16, 16), dim3(32, 8)>>>(wv, wvt, 512, 512);
    transpose_h_kernel<<<dim3(16, 16), dim3(32, 8)>>>(wp, wpt, 512, 512);
    transpose_h_kernel<<<dim3(16, 256), dim3(32, 8)>>>(w_sr, wsrt, KCONV, 512);

    qproj_tc<<<dim3(4, 128), 256>>>(x, bq);
    conv_tc<<<dim3(4, 8, CSPLIT), 256>>>(x);
    ln_kernel<<<BB * NKV, 128>>>(b_sr, gamma, beta);
    kv_tc<<<dim3(8, 8), 256>>>(bk, bv);
    attn_kernel<<<dim3(NQ / 64, BB * HEADS), 256, ATT_SMEM>>>();
    outproj_tc<<<dim3(4, 128), 256>>>(bp, out);
}

// round 5
// speedup vs baseline: 3.7362x; 1.0629x over previous
#include <cuda_runtime.h>
#include <cuda_fp16.h>
#include <math.h>
#include <stdint.h>

#define BB    4
#define NQ    4096
#define CC    512
#define HEADS 8
#define DH    64
#define NKV   256
#define KCONV 8192
#define CSPLIT 8

// ---------------------------------------------------------------------------
// Scratch
// ---------------------------------------------------------------------------
__device__ __half g_qh[BB * NQ * CC];
__device__ __half g_kh[BB * NKV * CC];
__device__ __half g_vh[BB * NKV * CC];
__device__ __half g_attnh[BB * NQ * CC];
__device__ float  g_xr[BB * NKV * CC];
__device__ float  g_xr_part[CSPLIT * BB * NKV * CC];

// ---------------------------------------------------------------------------
// helpers
// ---------------------------------------------------------------------------
__device__ __forceinline__ void mma_f16(float* c,
    uint32_t a0, uint32_t a1, uint32_t a2, uint32_t a3, uint32_t b0, uint32_t b1)
{
    asm volatile(
        "mma.sync.aligned.m16n8k16.row.col.f32.f16.f16.f32 "
        "{%0,%1,%2,%3},{%4,%5,%6,%7},{%8,%9},{%0,%1,%2,%3};"
        : "+f"(c[0]), "+f"(c[1]), "+f"(c[2]), "+f"(c[3])
        : "r"(a0), "r"(a1), "r"(a2), "r"(a3), "r"(b0), "r"(b1));
}

__device__ __forceinline__ uint4 pack8(float4 u, float4 v) {
    __half2 h0 = __floats2half2_rn(u.x, u.y);
    __half2 h1 = __floats2half2_rn(u.z, u.w);
    __half2 h2 = __floats2half2_rn(v.x, v.y);
    __half2 h3 = __floats2half2_rn(v.z, v.w);
    uint4 r;
    r.x = *(uint32_t*)&h0; r.y = *(uint32_t*)&h1;
    r.z = *(uint32_t*)&h2; r.w = *(uint32_t*)&h3;
    return r;
}

__device__ __forceinline__ uint32_t smem_u32(const void* p) {
    uint32_t a;
    asm("{ .reg .u64 t; cvta.to.shared.u64 t, %1; cvt.u32.u64 %0, t; }" : "=r"(a) : "l"(p));
    return a;
}

#define CP16(dst, src) \
    asm volatile("cp.async.cg.shared.global [%0], [%1], 16;" :: "r"(dst), "l"(src))
#define CPCOMMIT() asm volatile("cp.async.commit_group;" ::: "memory")
#define CPWAIT0()  asm volatile("cp.async.wait_group 0;" ::: "memory")

// ---------------------------------------------------------------------------
// fp16 mma.sync GEMM: 128x128 tile, K-step 32, cp.async double buffered.
// 256 threads = 8 warps; warp grid 2(m) x 4(n): warp tile 64x32.
// B read DIRECTLY from f32 [K][512] weights (no pre-transpose): staged f32
// in smem, fragment loader converts to half on the fly.
// AMODE: 0 = f32 A row-major, 1 = half A row-major, 2 = conv patch gather f32.
// ---------------------------------------------------------------------------
#define KS   32
#define AP   40
#define BPW  132
#define AS_BYTES (2 * 128 * AP * 2)          // 20480
#define BF_BYTES (2 * 32 * BPW * 4)          // 33792
#define GEMM_SMEM (AS_BYTES + BF_BYTES + 512)

template<int AMODE, bool OUTHALF, bool BIAS>
__device__ __forceinline__ void gemm_f16_body(
    const void* __restrict__ Ap_, long lda,
    const float* __restrict__ Bsrc, int kb,
    const float* __restrict__ bias,
    void* __restrict__ Cp, long ldc,
    int nkt, int bm, int bn, int z)
{
    extern __shared__ __align__(16) char smem[];
    __half (*As)[128][AP] = (__half(*)[128][AP])smem;
    float  (*Bf)[32][BPW] = (float(*)[32][BPW])(smem + AS_BYTES);
    float* sbias = (float*)(smem + AS_BYTES + BF_BYTES);

    const int tid = threadIdx.x;
    const int w = tid >> 5, l = tid & 31;
    const int g = l >> 2, t = l & 3;
    const int wm = (w >> 2) * 64;
    const int wn = (w & 3) * 32;

    if (BIAS && tid < 128) sbias[tid] = bias[bn + tid];

    const int r   = tid >> 1;          // 0..127  (A row)
    const int sgA = (tid & 1) * 16;    // 0 / 16  (A k-seg)

    const float* arow_f = nullptr;
    const __half* arow_h = nullptr;
    int pixbase = 0;
    if (AMODE == 1) {
        arow_h = (const __half*)Ap_ + (size_t)(bm + r) * lda;
    } else if (AMODE == 2) {
        const int gr = bm + r;
        pixbase = (gr >> 8) * 4096 + (((gr >> 4) & 15) << 8) + ((gr & 15) << 2);
    } else {
        arow_f = (const float*)Ap_ + (size_t)(bm + r) * lda;
    }

    const uint32_t sb = smem_u32(smem);

    float acc[4][4][4];
#pragma unroll
    for (int mi = 0; mi < 4; ++mi)
#pragma unroll
        for (int ni = 0; ni < 4; ++ni)
#pragma unroll
            for (int e = 0; e < 4; ++e) acc[mi][ni][e] = 0.f;

    uint4 aU0, aU1;

#define B_ASYNC(kt, buf) { \
    const int k0 = (kt) * KS; \
    _Pragma("unroll") \
    for (int i = 0; i < 4; ++i) { \
        const int idx = i * 1024 + tid * 4; \
        const int k = idx >> 7, n = idx & 127; \
        const float* src = Bsrc + (size_t)(kb + k0 + k) * 512 + bn + n; \
        const uint32_t dst = sb + AS_BYTES + (uint32_t)(((buf) * 32 + k) * BPW + n) * 4; \
        CP16(dst, src); \
    } }

#define A_ASYNC(kt, buf) { \
    const __half* p = arow_h + (kt) * KS + sgA; \
    const uint32_t dst = sb + (uint32_t)(((buf) * 128 + r) * AP + sgA) * 2; \
    CP16(dst, p); CP16(dst + 16, p + 8); }

#define A_LDG(kt) { \
    const float* p; \
    if (AMODE == 2) { \
        const int kl = (kt) * KS; \
        const int khw = z * 2 + (kl >> 9); \
        const int off = ((khw >> 2) << 6) | (khw & 3); \
        p = (const float*)Ap_ + (size_t)(pixbase + off) * 512 + (kl & 511) + sgA; \
    } else { \
        p = arow_f + (kt) * KS + sgA; \
    } \
    aU0 = pack8(*(const float4*)p, *(const float4*)(p + 4)); \
    aU1 = pack8(*(const float4*)(p + 8), *(const float4*)(p + 12)); }

#define A_STS(buf) { \
    *(uint4*)&As[buf][r][sgA]     = aU0; \
    *(uint4*)&As[buf][r][sgA + 8] = aU1; }

#define LOAD_STAGE_ISSUE(kt, buf) { \
    if (AMODE == 1) { A_ASYNC(kt, buf); } else { A_LDG(kt); } \
    B_ASYNC(kt, buf); CPCOMMIT(); }

#define LOAD_STAGE_FINISH(buf) { \
    if (AMODE != 1) { A_STS(buf); } \
    CPWAIT0(); }

    // prologue
    LOAD_STAGE_ISSUE(0, 0);
    LOAD_STAGE_FINISH(0);
    __syncthreads();

    for (int kt = 0; kt < nkt; ++kt) {
        const int buf = kt & 1;
        const bool nxt = (kt + 1) < nkt;
        if (nxt) LOAD_STAGE_ISSUE(kt + 1, buf ^ 1);

#pragma unroll
        for (int kk = 0; kk < 2; ++kk) {
            const int k16 = kk * 16 + 2 * t;
            uint32_t a[4][4];
#pragma unroll
            for (int mi = 0; mi < 4; ++mi) {
                const int rr = wm + mi * 16 + g;
                a[mi][0] = *(const uint32_t*)&As[buf][rr][k16];
                a[mi][1] = *(const uint32_t*)&As[buf][rr + 8][k16];
                a[mi][2] = *(const uint32_t*)&As[buf][rr][k16 + 8];
                a[mi][3] = *(const uint32_t*)&As[buf][rr + 8][k16 + 8];
            }
#pragma unroll
            for (int ni = 0; ni < 4; ++ni) {
                const int n = wn + ni * 8 + g;
                __half2 h0 = __floats2half2_rn(Bf[buf][k16][n],     Bf[buf][k16 + 1][n]);
                __half2 h1 = __floats2half2_rn(Bf[buf][k16 + 8][n], Bf[buf][k16 + 9][n]);
                const uint32_t b0 = *(uint32_t*)&h0;
                const uint32_t b1 = *(uint32_t*)&h1;
#pragma unroll
                for (int mi = 0; mi < 4; ++mi)
                    mma_f16(acc[mi][ni], a[mi][0], a[mi][1], a[mi][2], a[mi][3], b0, b1);
            }
        }
        if (nxt) LOAD_STAGE_FINISH(buf ^ 1);
        __syncthreads();
    }

#undef B_ASYNC
#undef A_ASYNC
#undef A_LDG
#undef A_STS
#undef LOAD_STAGE_ISSUE
#undef LOAD_STAGE_FINISH

    // epilogue (same mapping as R4)
#pragma unroll
    for (int mi = 0; mi < 4; ++mi) {
        const int r0 = bm + wm + mi * 16 + g;
#pragma unroll
        for (int ni = 0; ni < 4; ++ni) {
            const int cl = wn + ni * 8 + 2 * t;
            const int cn = bn + cl;
            float f0 = acc[mi][ni][0], f1 = acc[mi][ni][1];
            float f2 = acc[mi][ni][2], f3 = acc[mi][ni][3];
            if (BIAS) {
                const float b0 = sbias[cl], b1 = sbias[cl + 1];
                f0 += b0; f1 += b1; f2 += b0; f3 += b1;
            }
            if (OUTHALF) {
                __half* C = (__half*)Cp;
                *(__half2*)&C[(size_t)r0 * ldc + cn] = __floats2half2_rn(f0, f1);
                *(__half2*)&C[(size_t)(r0 + 8) * ldc + cn] = __floats2half2_rn(f2, f3);
            } else {
                float* C = (float*)Cp;
                *(float2*)&C[(size_t)r0 * ldc + cn] = make_float2(f0, f1);
                *(float2*)&C[(size_t)(r0 + 8) * ldc + cn] = make_float2(f2, f3);
            }
        }
    }
}

__global__ void __launch_bounds__(256) qproj_tc(const float* __restrict__ x,
                                                const float* __restrict__ wq,
                                                const float* __restrict__ bq)
{
    gemm_f16_body<0, true, true>(x, 512, wq, 0, bq, g_qh, 512, 16,
                                 blockIdx.y * 128, blockIdx.x * 128, 0);
}
__global__ void __launch_bounds__(256) kv_tc(const float* __restrict__ wk,
                                             const float* __restrict__ bk,
                                             const float* __restrict__ wv,
                                             const float* __restrict__ bv)
{
    const int sel = blockIdx.x >> 2;
    const int bn = (blockIdx.x & 3) * 128;
    if (sel == 0)
        gemm_f16_body<0, true, true>(g_xr, 512, wk, 0, bk, g_kh, 512, 16,
                                     blockIdx.y * 128, bn, 0);
    else
        gemm_f16_body<0, true, true>(g_xr, 512, wv, 0, bv, g_vh, 512, 16,
                                     blockIdx.y * 128, bn, 0);
}
__global__ void __launch_bounds__(256) outproj_tc(const float* __restrict__ wp,
                                                  const float* __restrict__ bp,
                                                  float* __restrict__ out)
{
    gemm_f16_body<1, false, true>(g_attnh, 512, wp, 0, bp, out, 512, 16,
                                  blockIdx.y * 128, blockIdx.x * 128, 0);
}
__global__ void __launch_bounds__(256) conv_tc(const float* __restrict__ x,
                                               const float* __restrict__ w_sr)
{
    const int z = blockIdx.z;
    gemm_f16_body<2, false, false>(x, 512, w_sr, z * 1024, nullptr,
                                   g_xr_part + (size_t)z * (BB * NKV * CC), 512, 32,
                                   blockIdx.y * 128, blockIdx.x * 128, z);
}

// ---------------------------------------------------------------------------
// split-K reduce + bias + LayerNorm
// ---------------------------------------------------------------------------
__global__ void ln_kernel(const float* __restrict__ bsr,
                          const float* __restrict__ gamma,
                          const float* __restrict__ beta)
{
    const int r = blockIdx.x;
    const int tid = threadIdx.x;
    float v[4];
    float s1 = 0.f, s2 = 0.f;
#pragma unroll
    for (int i = 0; i < 4; ++i) {
        const int c = tid + i * 128;
        const size_t off = (size_t)r * 512 + c;
        float tt = bsr[c];
#pragma unroll
        for (int p = 0; p < CSPLIT; ++p)
            tt += g_xr_part[(size_t)p * (BB * NKV * CC) + off];
        v[i] = tt;
        s1 += tt;
        s2 += tt * tt;
    }
#pragma unroll
    for (int o = 16; o > 0; o >>= 1) {
        s1 += __shfl_xor_sync(0xffffffffu, s1, o);
        s2 += __shfl_xor_sync(0xffffffffu, s2, o);
    }
    __shared__ float red[8];
    const int warp = tid >> 5, lane = tid & 31;
    if (lane == 0) { red[warp] = s1; red[warp + 4] = s2; }
    __syncthreads();
    s1 = red[0] + red[1] + red[2] + red[3];
    s2 = red[4] + red[5] + red[6] + red[7];
    const float mu = s1 * (1.f / 512.f);
    const float var = s2 * (1.f / 512.f) - mu * mu;
    const float rstd = rsqrtf(var + 1e-5f);
#pragma unroll
    for (int i = 0; i < 4; ++i) {
        const int c = tid + i * 128;
        g_xr[(size_t)r * 512 + c] = (v[i] - mu) * rstd * gamma[c] + beta[c];
    }
}

// ---------------------------------------------------------------------------
// Attention, fp16 mma.sync m16n8k16. CTA = 64 q x 256 kv per (b,h).
// (unchanged from R4 — verified correct)
// ---------------------------------------------------------------------------
#define QP 72
#define KP 72
#define VP 264
#define SP 264
#define PP 272
#define ATT_SMEM ((4608 + 18432 + 16896) * 2 + 16896 * 4)

__global__ void __launch_bounds__(256) attn_kernel()
{
    extern __shared__ __align__(1024) char smem[];
    __half* Qh = (__half*)smem;            // [64][QP]
    __half* Kh = Qh + 4608;                // [256][KP]
    __half* Vh = Qh + 23040;               // [64][VP]  (transposed V: Vh[d][kv])
    float*  S  = (float*)(smem + 79872);   // [64][SP]
    __half* Ph = Qh;                       // aliases Q/K after S computed [64][PP]

    const int tid = threadIdx.x;
    const int w = tid >> 5, l = tid & 31;
    const int g = l >> 2, t = l & 3;

    const int bh = blockIdx.y;
    const int b = bh >> 3, h = bh & 7;
    const int q0 = blockIdx.x * 64;
    const size_t qbase  = ((size_t)(b * NQ + q0)) * CC + h * DH;
    const size_t kvbase = ((size_t)(b * NKV)) * CC + h * DH;

#pragma unroll
    for (int i = 0; i < 2; ++i) {
        const int c = tid + i * 256;
        const int r = c >> 3, seg = (c & 7) * 8;
        *(uint4*)&Qh[r * QP + seg] = *(const uint4*)&g_qh[qbase + (size_t)r * CC + seg];
    }
#pragma unroll
    for (int i = 0; i < 8; ++i) {
        const int c = tid + i * 256;
        const int r = c >> 3, seg = (c & 7) * 8;
        *(uint4*)&Kh[r * KP + seg] = *(const uint4*)&g_kh[kvbase + (size_t)r * CC + seg];
    }
#pragma unroll
    for (int i = 0; i < 8; ++i) {
        const int c = tid + i * 256;
        const int kv = c >> 3, d0 = (c & 7) * 8;
        uint4 pk = *(const uint4*)&g_vh[kvbase + (size_t)kv * CC + d0];
        const __half* hv = (const __half*)&pk;
#pragma unroll
        for (int j = 0; j < 8; ++j)
            Vh[(d0 + j) * VP + kv] = hv[j];
    }
    __syncthreads();

    // S = Q K^T * scale
    {
        const int wm = (w >> 2) * 32;
        const int wn = (w & 3) * 64;
        float accS[2][8][4];
#pragma unroll
        for (int mi = 0; mi < 2; ++mi)
#pragma unroll
            for (int ni = 0; ni < 8; ++ni)
#pragma unroll
                for (int e = 0; e < 4; ++e) accS[mi][ni][e] = 0.f;

#pragma unroll
        for (int kk = 0; kk < 4; ++kk) {
            const int k0 = kk * 16;
            uint32_t a[2][4];
#pragma unroll
            for (int mi = 0; mi < 2; ++mi) {
                const int rr = wm + mi * 16 + g;
                a[mi][0] = *(const uint32_t*)&Qh[rr * QP + k0 + 2 * t];
                a[mi][1] = *(const uint32_t*)&Qh[(rr + 8) * QP + k0 + 2 * t];
                a[mi][2] = *(const uint32_t*)&Qh[rr * QP + k0 + 2 * t + 8];
                a[mi][3] = *(const uint32_t*)&Qh[(rr + 8) * QP + k0 + 2 * t + 8];
            }
#pragma unroll
            for (int ni = 0; ni < 8; ++ni) {
                const int n = wn + ni * 8 + g;
                const uint32_t b0 = *(const uint32_t*)&Kh[n * KP + k0 + 2 * t];
                const uint32_t b1 = *(const uint32_t*)&Kh[n * KP + k0 + 2 * t + 8];
#pragma unroll
                for (int mi = 0; mi < 2; ++mi)
                    mma_f16(accS[mi][ni], a[mi][0], a[mi][1], a[mi][2], a[mi][3], b0, b1);
            }
        }
        const float sc = 0.125f;
#pragma unroll
        for (int mi = 0; mi < 2; ++mi) {
            const int rr = wm + mi * 16 + g;
#pragma unroll
            for (int ni = 0; ni < 8; ++ni) {
                const int cn = wn + ni * 8 + 2 * t;
                *(float2*)&S[rr * SP + cn] = make_float2(accS[mi][ni][0] * sc, accS[mi][ni][1] * sc);
                *(float2*)&S[(rr + 8) * SP + cn] = make_float2(accS[mi][ni][2] * sc, accS[mi][ni][3] * sc);
            }
        }
    }
    __syncthreads();

    // softmax -> Ph (half)
    for (int r = w; r < 64; r += 8) {
        float* row = &S[r * SP];
        float m = -1e30f;
#pragma unroll
        for (int j = 0; j < 8; ++j) m = fmaxf(m, row[l + j * 32]);
#pragma unroll
        for (int o = 16; o > 0; o >>= 1) m = fmaxf(m, __shfl_xor_sync(0xffffffffu, m, o));
        float s = 0.f;
        float e[8];
#pragma unroll
        for (int j = 0; j < 8; ++j) {
            e[j] = __expf(row[l + j * 32] - m);
            s += e[j];
        }
#pragma unroll
        for (int o = 16; o > 0; o >>= 1) s += __shfl_xor_sync(0xffffffffu, s, o);
        const float inv = 1.f / s;
#pragma unroll
        for (int j = 0; j < 8; ++j)
            Ph[r * PP + l + j * 32] = __float2half(e[j] * inv);
    }
    __syncthreads();

    // O = P @ V
    {
        const int wm = (w >> 2) * 32;
        const int wn = (w & 3) * 16;
        float accO[2][2][4];
#pragma unroll
        for (int mi = 0; mi < 2; ++mi)
#pragma unroll
            for (int ni = 0; ni < 2; ++ni)
#pragma unroll
                for (int e2 = 0; e2 < 4; ++e2) accO[mi][ni][e2] = 0.f;

#pragma unroll
        for (int kk = 0; kk < 16; ++kk) {
            const int k0 = kk * 16;
            uint32_t a[2][4];
#pragma unroll
            for (int mi = 0; mi < 2; ++mi) {
                const int rr = wm + mi * 16 + g;
                a[mi][0] = *(const uint32_t*)&Ph[rr * PP + k0 + 2 * t];
                a[mi][1] = *(const uint32_t*)&Ph[(rr + 8) * PP + k0 + 2 * t];
                a[mi][2] = *(const uint32_t*)&Ph[rr * PP + k0 + 2 * t + 8];
                a[mi][3] = *(const uint32_t*)&Ph[(rr + 8) * PP + k0 + 2 * t + 8];
            }
#pragma unroll
            for (int ni = 0; ni < 2; ++ni) {
                const int n = wn + ni * 8 + g;
                const uint32_t b0 = *(const uint32_t*)&Vh[n * VP + k0 + 2 * t];
                const uint32_t b1 = *(const uint32_t*)&Vh[n * VP + k0 + 2 * t + 8];
#pragma unroll
                for (int mi = 0; mi < 2; ++mi)
                    mma_f16(accO[mi][ni], a[mi][0], a[mi][1], a[mi][2], a[mi][3], b0, b1);
            }
        }
#pragma unroll
        for (int mi = 0; mi < 2; ++mi) {
            const int rr = wm + mi * 16 + g;
#pragma unroll
            for (int ni = 0; ni < 2; ++ni) {
                const int cn = wn + ni * 8 + 2 * t;
                *(__half2*)&g_attnh[qbase + (size_t)rr * CC + cn] =
                    __floats2half2_rn(accO[mi][ni][0], accO[mi][ni][1]);
                *(__half2*)&g_attnh[qbase + (size_t)(rr + 8) * CC + cn] =
                    __floats2half2_rn(accO[mi][ni][2], accO[mi][ni][3]);
            }
        }
    }
}

// ---------------------------------------------------------------------------
extern "C" void kernel_launch(void* const* d_in, const int* in_sizes, int n_in,
                              void* d_out, int out_size)
{
    (void)in_sizes; (void)n_in; (void)out_size;
    const float* x     = (const float*)d_in[0];
    const float* wq    = (const float*)d_in[1];
    const float* bq    = (const float*)d_in[2];
    const float* wk    = (const float*)d_in[3];
    const float* bk    = (const float*)d_in[4];
    const float* wv    = (const float*)d_in[5];
    const float* bv    = (const float*)d_in[6];
    const float* w_sr  = (const float*)d_in[7];
    const float* b_sr  = (const float*)d_in[8];
    const float* gamma = (const float*)d_in[9];
    const float* beta  = (const float*)d_in[10];
    const float* wp    = (const float*)d_in[11];
    const float* bp    = (const float*)d_in[12];
    float* out = (float*)d_out;

    cudaFuncSetAttribute(qproj_tc,   cudaFuncAttributeMaxDynamicSharedMemorySize, GEMM_SMEM);
    cudaFuncSetAttribute(kv_tc,      cudaFuncAttributeMaxDynamicSharedMemorySize, GEMM_SMEM);
    cudaFuncSetAttribute(outproj_tc, cudaFuncAttributeMaxDynamicSharedMemorySize, GEMM_SMEM);
    cudaFuncSetAttribute(conv_tc,    cudaFuncAttributeMaxDynamicSharedMemorySize, GEMM_SMEM);
    cudaFuncSetAttribute(attn_kernel, cudaFuncAttributeMaxDynamicSharedMemorySize, ATT_SMEM);

    qproj_tc<<<dim3(4, 128), 256, GEMM_SMEM>>>(x, wq, bq);
    conv_tc<<<dim3(4, 8, CSPLIT), 256, GEMM_SMEM>>>(x, w_sr);
    ln_kernel<<<BB * NKV, 128>>>(b_sr, gamma, beta);
    kv_tc<<<dim3(8, 8), 256, GEMM_SMEM>>>(wk, bk, wv, bv);
    attn_kernel<<<dim3(NQ / 64, BB * HEADS), 256, ATT_SMEM>>>();
    outproj_tc<<<dim3(4, 128), 256, GEMM_SMEM>>>(wp, bp, out);
}

// round 7
// speedup vs baseline: 4.3189x; 1.1559x over previous
#include <cuda_runtime.h>
#include <cuda_fp16.h>
#include <math.h>
#include <stdint.h>

#define BB    4
#define NQ    4096
#define CC    512
#define HEADS 8
#define DH    64
#define NKV   256
#define KCONV 8192
#define CSPLIT 16

// ---------------------------------------------------------------------------
// Scratch
// ---------------------------------------------------------------------------
__device__ __half g_xh[BB * NQ * CC];               // x in fp16
__device__ __half g_qh[BB * NQ * CC];
__device__ __half g_kh[BB * NKV * CC];
__device__ __half g_vh[BB * NKV * CC];
__device__ __half g_attnh[BB * NQ * CC];
__device__ __half g_xrh[BB * NKV * CC];             // layernorm output (fp16)
__device__ float  g_xr_part[CSPLIT * BB * NKV * CC];

// ---------------------------------------------------------------------------
// helpers
// ---------------------------------------------------------------------------
__device__ __forceinline__ void mma_f16(float* c,
    uint32_t a0, uint32_t a1, uint32_t a2, uint32_t a3, uint32_t b0, uint32_t b1)
{
    asm volatile(
        "mma.sync.aligned.m16n8k16.row.col.f32.f16.f16.f32 "
        "{%0,%1,%2,%3},{%4,%5,%6,%7},{%8,%9},{%0,%1,%2,%3};"
        : "+f"(c[0]), "+f"(c[1]), "+f"(c[2]), "+f"(c[3])
        : "r"(a0), "r"(a1), "r"(a2), "r"(a3), "r"(b0), "r"(b1));
}

__device__ __forceinline__ void ldsm_x4(uint32_t addr,
    uint32_t& r0, uint32_t& r1, uint32_t& r2, uint32_t& r3)
{
    asm volatile("ldmatrix.sync.aligned.m8n8.x4.shared.b16 {%0,%1,%2,%3}, [%4];"
        : "=r"(r0), "=r"(r1), "=r"(r2), "=r"(r3) : "r"(addr));
}

__device__ __forceinline__ uint32_t smem_u32(const void* p) {
    uint32_t a;
    asm("{ .reg .u64 t; cvta.to.shared.u64 t, %1; cvt.u32.u64 %0, t; }" : "=r"(a) : "l"(p));
    return a;
}

#define CP16(dst, src) \
    asm volatile("cp.async.cg.shared.global [%0], [%1], 16;" :: "r"(dst), "l"(src))
#define CPCOMMIT() asm volatile("cp.async.commit_group;" ::: "memory")

// ---------------------------------------------------------------------------
// fp16 GEMM core: 128x128 tile, K-step 32, 4-stage cp.async pipeline,
// ldmatrix A fragments. 256 threads = 8 warps, warp grid 2(m) x 4(n).
// A: fp16 row-major (per-thread row pointer). B: fp32 [K][512], staged raw,
// converted to half in the fragment loader (conflict-free, BPW=132).
// ---------------------------------------------------------------------------
#define NSTAGE 4
#define AP   40
#define BPW  132
#define B_OFF 10240                    // A stage bytes: 128*40*2
#define STAGE_BYTES (10240 + 16896)    // + B stage: 32*132*4
#define GEMM_SMEM (NSTAGE * STAGE_BYTES + 512)

template<bool OUTHALF, bool BIAS>
__device__ __forceinline__ void gemm_core(
    const __half* __restrict__ arow,   // per-thread A row base
    const float* __restrict__ Bk,      // B base (kb folded in): [k][512]
    const float* __restrict__ bias,
    void* __restrict__ Cp, int ldc,
    int nkt, int bm, int bn)
{
    extern __shared__ __align__(16) char smem[];
    float* sbias = (float*)(smem + NSTAGE * STAGE_BYTES);

    const int tid = threadIdx.x;
    const int w = tid >> 5, l = tid & 31;
    const int g = l >> 2, t = l & 3;
    const int wm = (w >> 2) * 64;
    const int wn = (w & 3) * 32;

    if (BIAS && tid < 128) sbias[tid] = bias[bn + tid];

    const int r   = tid >> 1;
    const int sgA = (tid & 1) * 16;
    const uint32_t sb = smem_u32(smem);
    // ldmatrix thread base within A stage
    const uint32_t a_tb = (uint32_t)(((wm + (l & 15)) * AP + ((l >> 4) << 3)) * 2);

    float acc[4][4][4];
#pragma unroll
    for (int mi = 0; mi < 4; ++mi)
#pragma unroll
        for (int ni = 0; ni < 4; ++ni)
#pragma unroll
            for (int e = 0; e < 4; ++e) acc[mi][ni][e] = 0.f;

// NOTE: all macro-internal identifiers use reserved _-prefixed names so the
// macro argument can never be shadowed by them (R6 bug: ISSUE(s) self-shadow).
#define ISSUE(ktArg) { \
    const int _st = (ktArg) & (NSTAGE - 1); \
    const uint32_t _ab = sb + _st * STAGE_BYTES; \
    const __half* _ap = arow + (ktArg) * 32 + sgA; \
    const uint32_t _ad = _ab + (uint32_t)(r * AP + sgA) * 2; \
    CP16(_ad, _ap); CP16(_ad + 16, _ap + 8); \
    const uint32_t _bb = _ab + B_OFF; \
    const float* _bp = Bk + (size_t)((ktArg) * 32) * 512 + bn; \
    _Pragma("unroll") \
    for (int _i = 0; _i < 4; ++_i) { \
        const int _ix = _i * 1024 + tid * 4; \
        const int _k = _ix >> 7, _n = _ix & 127; \
        CP16(_bb + (uint32_t)(_k * BPW + _n) * 4, _bp + (size_t)_k * 512 + _n); \
    } }

    // prologue: fill NSTAGE-1 stages
#pragma unroll
    for (int ps = 0; ps < NSTAGE - 1; ++ps) {
        if (ps < nkt) ISSUE(ps);
        CPCOMMIT();
    }

    for (int kt = 0; kt < nkt; ++kt) {
        const int buf = kt & (NSTAGE - 1);
        asm volatile("cp.async.wait_group %0;" :: "n"(NSTAGE - 2) : "memory");
        __syncthreads();
        if (kt + NSTAGE - 1 < nkt) ISSUE(kt + NSTAGE - 1);
        CPCOMMIT();

        const uint32_t abase = sb + buf * STAGE_BYTES;
        const float* Bf = (const float*)(smem + buf * STAGE_BYTES + B_OFF);

#pragma unroll
        for (int kk = 0; kk < 2; ++kk) {
            const int k16 = kk * 16 + 2 * t;
            uint32_t a[4][4];
#pragma unroll
            for (int mi = 0; mi < 4; ++mi)
                ldsm_x4(abase + a_tb + (uint32_t)(mi * 16 * AP * 2 + kk * 32),
                        a[mi][0], a[mi][1], a[mi][2], a[mi][3]);
#pragma unroll
            for (int ni = 0; ni < 4; ++ni) {
                const int n = wn + ni * 8 + g;
                __half2 h0 = __floats2half2_rn(Bf[k16 * BPW + n],       Bf[(k16 + 1) * BPW + n]);
                __half2 h1 = __floats2half2_rn(Bf[(k16 + 8) * BPW + n], Bf[(k16 + 9) * BPW + n]);
                const uint32_t b0 = *(uint32_t*)&h0;
                const uint32_t b1 = *(uint32_t*)&h1;
#pragma unroll
                for (int mi = 0; mi < 4; ++mi)
                    mma_f16(acc[mi][ni], a[mi][0], a[mi][1], a[mi][2], a[mi][3], b0, b1);
            }
        }
        __syncthreads();
    }
#undef ISSUE

#pragma unroll
    for (int mi = 0; mi < 4; ++mi) {
        const int r0 = bm + wm + mi * 16 + g;
#pragma unroll
        for (int ni = 0; ni < 4; ++ni) {
            const int cl = wn + ni * 8 + 2 * t;
            const int cn = bn + cl;
            float f0 = acc[mi][ni][0], f1 = acc[mi][ni][1];
            float f2 = acc[mi][ni][2], f3 = acc[mi][ni][3];
            if (BIAS) {
                const float b0 = sbias[cl], b1 = sbias[cl + 1];
                f0 += b0; f1 += b1; f2 += b0; f3 += b1;
            }
            if (OUTHALF) {
                __half* C = (__half*)Cp;
                *(__half2*)&C[(size_t)r0 * ldc + cn] = __floats2half2_rn(f0, f1);
                *(__half2*)&C[(size_t)(r0 + 8) * ldc + cn] = __floats2half2_rn(f2, f3);
            } else {
                float* C = (float*)Cp;
                *(float2*)&C[(size_t)r0 * ldc + cn] = make_float2(f0, f1);
                *(float2*)&C[(size_t)(r0 + 8) * ldc + cn] = make_float2(f2, f3);
            }
        }
    }
}

// ---------------------------------------------------------------------------
// merged qproj + conv kernel: grid 1024
// ---------------------------------------------------------------------------
__global__ void __launch_bounds__(256) qc_tc(const float* __restrict__ wq,
                                             const float* __restrict__ bq,
                                             const float* __restrict__ w_sr)
{
    const int bid = blockIdx.x;
    const int tid = threadIdx.x;
    const int r = tid >> 1;
    if (bid < 512) {
        const int bm = (bid >> 2) * 128, bn = (bid & 3) * 128;
        const __half* arow = g_xh + (size_t)(bm + r) * 512;
        gemm_core<true, true>(arow, wq, bq, g_qh, 512, 16, bm, bn);
    } else {
        const int c = bid - 512;
        const int z = c >> 5, tl = c & 31;
        const int bm = (tl >> 2) * 128, bn = (tl & 3) * 128;
        const int gr = bm + r;
        const int pix = (gr >> 8) * 4096 + (((gr >> 4) & 15) << 8) + ((gr & 15) << 2);
        const int off = ((z >> 2) << 6) | (z & 3);
        const __half* arow = g_xh + (size_t)(pix + off) * 512;
        gemm_core<false, false>(arow, w_sr + (size_t)z * 512 * 512, nullptr,
                                g_xr_part + (size_t)z * (BB * NKV * CC), 512, 16, bm, bn);
    }
}

__global__ void __launch_bounds__(256) kv_tc(const float* __restrict__ wk,
                                             const float* __restrict__ bk,
                                             const float* __restrict__ wv,
                                             const float* __restrict__ bv)
{
    const int bid = blockIdx.x;
    const int sel = bid >> 5;
    const int tl = bid & 31;
    const int bm = (tl >> 2) * 128, bn = (tl & 3) * 128;
    const __half* arow = g_xrh + (size_t)(bm + (threadIdx.x >> 1)) * 512;
    if (sel == 0)
        gemm_core<true, true>(arow, wk, bk, g_kh, 512, 16, bm, bn);
    else
        gemm_core<true, true>(arow, wv, bv, g_vh, 512, 16, bm, bn);
}

__global__ void __launch_bounds__(256) outproj_tc(const float* __restrict__ wp,
                                                  const float* __restrict__ bp,
                                                  float* __restrict__ out)
{
    const int bid = blockIdx.x;
    const int bm = (bid >> 2) * 128, bn = (bid & 3) * 128;
    const __half* arow = g_attnh + (size_t)(bm + (threadIdx.x >> 1)) * 512;
    gemm_core<false, true>(arow, wp, bp, out, 512, 16, bm, bn);
}

// ---------------------------------------------------------------------------
// x -> fp16 convert
// ---------------------------------------------------------------------------
__global__ void xconv_kernel(const float* __restrict__ x)
{
    const size_t i = ((size_t)blockIdx.x * blockDim.x + threadIdx.x) * 8;
    float4 u = *(const float4*)&x[i];
    float4 v = *(const float4*)&x[i + 4];
    __half2 h0 = __floats2half2_rn(u.x, u.y);
    __half2 h1 = __floats2half2_rn(u.z, u.w);
    __half2 h2 = __floats2half2_rn(v.x, v.y);
    __half2 h3 = __floats2half2_rn(v.z, v.w);
    uint4 pk;
    pk.x = *(uint32_t*)&h0; pk.y = *(uint32_t*)&h1;
    pk.z = *(uint32_t*)&h2; pk.w = *(uint32_t*)&h3;
    *(uint4*)&g_xh[i] = pk;
}

// ---------------------------------------------------------------------------
// split-K reduce + bias + LayerNorm -> fp16
// ---------------------------------------------------------------------------
__global__ void ln_kernel(const float* __restrict__ bsr,
                          const float* __restrict__ gamma,
                          const float* __restrict__ beta)
{
    const int r = blockIdx.x;
    const int tid = threadIdx.x;
    float v[4];
    float s1 = 0.f, s2 = 0.f;
#pragma unroll
    for (int i = 0; i < 4; ++i) {
        const int c = tid + i * 128;
        const size_t off = (size_t)r * 512 + c;
        float tt = bsr[c];
#pragma unroll
        for (int p = 0; p < CSPLIT; ++p)
            tt += g_xr_part[(size_t)p * (BB * NKV * CC) + off];
        v[i] = tt;
        s1 += tt;
        s2 += tt * tt;
    }
#pragma unroll
    for (int o = 16; o > 0; o >>= 1) {
        s1 += __shfl_xor_sync(0xffffffffu, s1, o);
        s2 += __shfl_xor_sync(0xffffffffu, s2, o);
    }
    __shared__ float red[8];
    const int warp = tid >> 5, lane = tid & 31;
    if (lane == 0) { red[warp] = s1; red[warp + 4] = s2; }
    __syncthreads();
    s1 = red[0] + red[1] + red[2] + red[3];
    s2 = red[4] + red[5] + red[6] + red[7];
    const float mu = s1 * (1.f / 512.f);
    const float var = s2 * (1.f / 512.f) - mu * mu;
    const float rstd = rsqrtf(var + 1e-5f);
#pragma unroll
    for (int i = 0; i < 4; ++i) {
        const int c = tid + i * 128;
        g_xrh[(size_t)r * 512 + c] = __float2half((v[i] - mu) * rstd * gamma[c] + beta[c]);
    }
}

// ---------------------------------------------------------------------------
// Attention (unchanged — verified in R4/R5)
// ---------------------------------------------------------------------------
#define QP 72
#define KP 72
#define VP 264
#define SP 264
#define PP 272
#define ATT_SMEM ((4608 + 18432 + 16896) * 2 + 16896 * 4)

__global__ void __launch_bounds__(256) attn_kernel()
{
    extern __shared__ __align__(1024) char smem[];
    __half* Qh = (__half*)smem;
    __half* Kh = Qh + 4608;
    __half* Vh = Qh + 23040;
    float*  S  = (float*)(smem + 79872);
    __half* Ph = Qh;

    const int tid = threadIdx.x;
    const int w = tid >> 5, l = tid & 31;
    const int g = l >> 2, t = l & 3;

    const int bh = blockIdx.y;
    const int b = bh >> 3, h = bh & 7;
    const int q0 = blockIdx.x * 64;
    const size_t qbase  = ((size_t)(b * NQ + q0)) * CC + h * DH;
    const size_t kvbase = ((size_t)(b * NKV)) * CC + h * DH;

#pragma unroll
    for (int i = 0; i < 2; ++i) {
        const int c = tid + i * 256;
        const int r = c >> 3, seg = (c & 7) * 8;
        *(uint4*)&Qh[r * QP + seg] = *(const uint4*)&g_qh[qbase + (size_t)r * CC + seg];
    }
#pragma unroll
    for (int i = 0; i < 8; ++i) {
        const int c = tid + i * 256;
        const int r = c >> 3, seg = (c & 7) * 8;
        *(uint4*)&Kh[r * KP + seg] = *(const uint4*)&g_kh[kvbase + (size_t)r * CC + seg];
    }
#pragma unroll
    for (int i = 0; i < 8; ++i) {
        const int c = tid + i * 256;
        const int kv = c >> 3, d0 = (c & 7) * 8;
        uint4 pk = *(const uint4*)&g_vh[kvbase + (size_t)kv * CC + d0];
        const __half* hv = (const __half*)&pk;
#pragma unroll
        for (int j = 0; j < 8; ++j)
            Vh[(d0 + j) * VP + kv] = hv[j];
    }
    __syncthreads();

    {
        const int wm = (w >> 2) * 32;
        const int wn = (w & 3) * 64;
        float accS[2][8][4];
#pragma unroll
        for (int mi = 0; mi < 2; ++mi)
#pragma unroll
            for (int ni = 0; ni < 8; ++ni)
#pragma unroll
                for (int e = 0; e < 4; ++e) accS[mi][ni][e] = 0.f;

#pragma unroll
        for (int kk = 0; kk < 4; ++kk) {
            const int k0 = kk * 16;
            uint32_t a[2][4];
#pragma unroll
            for (int mi = 0; mi < 2; ++mi) {
                const int rr = wm + mi * 16 + g;
                a[mi][0] = *(const uint32_t*)&Qh[rr * QP + k0 + 2 * t];
                a[mi][1] = *(const uint32_t*)&Qh[(rr + 8) * QP + k0 + 2 * t];
                a[mi][2] = *(const uint32_t*)&Qh[rr * QP + k0 + 2 * t + 8];
                a[mi][3] = *(const uint32_t*)&Qh[(rr + 8) * QP + k0 + 2 * t + 8];
            }
#pragma unroll
            for (int ni = 0; ni < 8; ++ni) {
                const int n = wn + ni * 8 + g;
                const uint32_t b0 = *(const uint32_t*)&Kh[n * KP + k0 + 2 * t];
                const uint32_t b1 = *(const uint32_t*)&Kh[n * KP + k0 + 2 * t + 8];
#pragma unroll
                for (int mi = 0; mi < 2; ++mi)
                    mma_f16(accS[mi][ni], a[mi][0], a[mi][1], a[mi][2], a[mi][3], b0, b1);
            }
        }
        const float sc = 0.125f;
#pragma unroll
        for (int mi = 0; mi < 2; ++mi) {
            const int rr = wm + mi * 16 + g;
#pragma unroll
            for (int ni = 0; ni < 8; ++ni) {
                const int cn = wn + ni * 8 + 2 * t;
                *(float2*)&S[rr * SP + cn] = make_float2(accS[mi][ni][0] * sc, accS[mi][ni][1] * sc);
                *(float2*)&S[(rr + 8) * SP + cn] = make_float2(accS[mi][ni][2] * sc, accS[mi][ni][3] * sc);
            }
        }
    }
    __syncthreads();

    for (int r = w; r < 64; r += 8) {
        float* row = &S[r * SP];
        float m = -1e30f;
#pragma unroll
        for (int j = 0; j < 8; ++j) m = fmaxf(m, row[l + j * 32]);
#pragma unroll
        for (int o = 16; o > 0; o >>= 1) m = fmaxf(m, __shfl_xor_sync(0xffffffffu, m, o));
        float s = 0.f;
        float e[8];
#pragma unroll
        for (int j = 0; j < 8; ++j) {
            e[j] = __expf(row[l + j * 32] - m);
            s += e[j];
        }
#pragma unroll
        for (int o = 16; o > 0; o >>= 1) s += __shfl_xor_sync(0xffffffffu, s, o);
        const float inv = 1.f / s;
#pragma unroll
        for (int j = 0; j < 8; ++j)
            Ph[r * PP + l + j * 32] = __float2half(e[j] * inv);
    }
    __syncthreads();

    {
        const int wm = (w >> 2) * 32;
        const int wn = (w & 3) * 16;
        float accO[2][2][4];
#pragma unroll
        for (int mi = 0; mi < 2; ++mi)
#pragma unroll
            for (int ni = 0; ni < 2; ++ni)
#pragma unroll
                for (int e2 = 0; e2 < 4; ++e2) accO[mi][ni][e2] = 0.f;

#pragma unroll
        for (int kk = 0; kk < 16; ++kk) {
            const int k0 = kk * 16;
            uint32_t a[2][4];
#pragma unroll
            for (int mi = 0; mi < 2; ++mi) {
                const int rr = wm + mi * 16 + g;
                a[mi][0] = *(const uint32_t*)&Ph[rr * PP + k0 + 2 * t];
                a[mi][1] = *(const uint32_t*)&Ph[(rr + 8) * PP + k0 + 2 * t];
                a[mi][2] = *(const uint32_t*)&Ph[rr * PP + k0 + 2 * t + 8];
                a[mi][3] = *(const uint32_t*)&Ph[(rr + 8) * PP + k0 + 2 * t + 8];
            }
#pragma unroll
            for (int ni = 0; ni < 2; ++ni) {
                const int n = wn + ni * 8 + g;
                const uint32_t b0 = *(const uint32_t*)&Vh[n * VP + k0 + 2 * t];
                const uint32_t b1 = *(const uint32_t*)&Vh[n * VP + k0 + 2 * t + 8];
#pragma unroll
                for (int mi = 0; mi < 2; ++mi)
                    mma_f16(accO[mi][ni], a[mi][0], a[mi][1], a[mi][2], a[mi][3], b0, b1);
            }
        }
#pragma unroll
        for (int mi = 0; mi < 2; ++mi) {
            const int rr = wm + mi * 16 + g;
#pragma unroll
            for (int ni = 0; ni < 2; ++ni) {
                const int cn = wn + ni * 8 + 2 * t;
                *(__half2*)&g_attnh[qbase + (size_t)rr * CC + cn] =
                    __floats2half2_rn(accO[mi][ni][0], accO[mi][ni][1]);
                *(__half2*)&g_attnh[qbase + (size_t)(rr + 8) * CC + cn] =
                    __floats2half2_rn(accO[mi][ni][2], accO[mi][ni][3]);
            }
        }
    }
}

// ---------------------------------------------------------------------------
extern "C" void kernel_launch(void* const* d_in, const int* in_sizes, int n_in,
                              void* d_out, int out_size)
{
    (void)in_sizes; (void)n_in; (void)out_size;
    const float* x     = (const float*)d_in[0];
    const float* wq    = (const float*)d_in[1];
    const float* bq    = (const float*)d_in[2];
    const float* wk    = (const float*)d_in[3];
    const float* bk    = (const float*)d_in[4];
    const float* wv    = (const float*)d_in[5];
    const float* bv    = (const float*)d_in[6];
    const float* w_sr  = (const float*)d_in[7];
    const float* b_sr  = (const float*)d_in[8];
    const float* gamma = (const float*)d_in[9];
    const float* beta  = (const float*)d_in[10];
    const float* wp    = (const float*)d_in[11];
    const float* bp    = (const float*)d_in[12];
    float* out = (float*)d_out;

    cudaFuncSetAttribute(qc_tc,      cudaFuncAttributeMaxDynamicSharedMemorySize, GEMM_SMEM);
    cudaFuncSetAttribute(kv_tc,      cudaFuncAttributeMaxDynamicSharedMemorySize, GEMM_SMEM);
    cudaFuncSetAttribute(outproj_tc, cudaFuncAttributeMaxDynamicSharedMemorySize, GEMM_SMEM);
    cudaFuncSetAttribute(attn_kernel, cudaFuncAttributeMaxDynamicSharedMemorySize, ATT_SMEM);

    xconv_kernel<<<BB * NQ * CC / (256 * 8), 256>>>(x);
    qc_tc<<<1024, 256, GEMM_SMEM>>>(wq, bq, w_sr);
    ln_kernel<<<BB * NKV, 128>>>(b_sr, gamma, beta);
    kv_tc<<<64, 256, GEMM_SMEM>>>(wk, bk, wv, bv);
    attn_kernel<<<dim3(NQ / 64, BB * HEADS), 256, ATT_SMEM>>>();
    outproj_tc<<<512, 256, GEMM_SMEM>>>(wp, bp, out);
}

// round 9
// speedup vs baseline: 4.7895x; 1.1090x over previous
#include <cuda_runtime.h>
#include <cuda_fp16.h>
#include <math.h>
#include <stdint.h>

#define BB    4
#define NQ    4096
#define CC    512
#define HEADS 8
#define DH    64
#define NKV   256
#define KCONV 8192
#define CSPLIT 16

// ---------------------------------------------------------------------------
// Scratch
// ---------------------------------------------------------------------------
__device__ __half g_xh[BB * NQ * CC];
__device__ __half g_qh[BB * NQ * CC];
__device__ __half g_kh[BB * NKV * CC];
__device__ __half g_vh[BB * NKV * CC];
__device__ __half g_attnh[BB * NQ * CC];
__device__ __half g_xrh[BB * NKV * CC];
__device__ float  g_xr_part[CSPLIT * BB * NKV * CC];
// fp16 weights (same [K][N] layout as the fp32 originals)
__device__ __half g_wqh[CC * CC];
__device__ __half g_wkh[CC * CC];
__device__ __half g_wvh[CC * CC];
__device__ __half g_wph[CC * CC];
__device__ __half g_wsrh[(size_t)KCONV * CC];

// ---------------------------------------------------------------------------
// helpers
// ---------------------------------------------------------------------------
__device__ __forceinline__ void mma_f16(float* c,
    uint32_t a0, uint32_t a1, uint32_t a2, uint32_t a3, uint32_t b0, uint32_t b1)
{
    asm volatile(
        "mma.sync.aligned.m16n8k16.row.col.f32.f16.f16.f32 "
        "{%0,%1,%2,%3},{%4,%5,%6,%7},{%8,%9},{%0,%1,%2,%3};"
        : "+f"(c[0]), "+f"(c[1]), "+f"(c[2]), "+f"(c[3])
        : "r"(a0), "r"(a1), "r"(a2), "r"(a3), "r"(b0), "r"(b1));
}

__device__ __forceinline__ void ldsm_x4(uint32_t addr,
    uint32_t& r0, uint32_t& r1, uint32_t& r2, uint32_t& r3)
{
    asm volatile("ldmatrix.sync.aligned.m8n8.x4.shared.b16 {%0,%1,%2,%3}, [%4];"
        : "=r"(r0), "=r"(r1), "=r"(r2), "=r"(r3) : "r"(addr));
}

__device__ __forceinline__ void ldsm_x4_t(uint32_t addr,
    uint32_t& r0, uint32_t& r1, uint32_t& r2, uint32_t& r3)
{
    asm volatile("ldmatrix.sync.aligned.m8n8.x4.trans.shared.b16 {%0,%1,%2,%3}, [%4];"
        : "=r"(r0), "=r"(r1), "=r"(r2), "=r"(r3) : "r"(addr));
}

__device__ __forceinline__ uint32_t smem_u32(const void* p) {
    uint32_t a;
    asm("{ .reg .u64 t; cvta.to.shared.u64 t, %1; cvt.u32.u64 %0, t; }" : "=r"(a) : "l"(p));
    return a;
}

#define CP16(dst, src) \
    asm volatile("cp.async.cg.shared.global [%0], [%1], 16;" :: "r"(dst), "l"(src))
#define CPCOMMIT() asm volatile("cp.async.commit_group;" ::: "memory")

// ---------------------------------------------------------------------------
// fp16 GEMM core: 128x128 tile, K-step 32, 4-stage cp.async, all-fp16 smem.
// A fragments: ldmatrix; B fragments: ldmatrix.trans on [k][n] tile.
// 256 threads = 8 warps, warp grid 2(m) x 4(n), warp tile 64x32.
// ---------------------------------------------------------------------------
#define NSTAGE 4
#define AP   40
#define BP2  136
#define A_BYTES (128 * AP * 2)            // 10240
#define B_OFF   A_BYTES
#define STAGE_BYTES (A_BYTES + 32 * BP2 * 2)   // 10240 + 8704 = 18944
#define GEMM_SMEM (NSTAGE * STAGE_BYTES + 512)

template<bool OUTHALF, bool BIAS>
__device__ __forceinline__ void gemm_core(
    const __half* __restrict__ arow,   // per-thread A row base
    const __half* __restrict__ Bk,     // fp16 B base: [k][512], kb folded in
    const float* __restrict__ bias,
    void* __restrict__ Cp, int ldc,
    int nkt, int bm, int bn)
{
    extern __shared__ __align__(16) char smem[];
    float* sbias = (float*)(smem + NSTAGE * STAGE_BYTES);

    const int tid = threadIdx.x;
    const int w = tid >> 5, l = tid & 31;
    const int g = l >> 2, t = l & 3;
    const int wm = (w >> 2) * 64;
    const int wn = (w & 3) * 32;

    if (BIAS && tid < 128) sbias[tid] = bias[bn + tid];

    const int r   = tid >> 1;
    const int sgA = (tid & 1) * 16;
    // B staging coords: exactly 32 rows x 128 cols (512 CP16 total)
    const int bK = tid >> 3;           // 0..31
    const int bN = (tid & 7) * 16;     // 0..112
    const uint32_t sb = smem_u32(smem);
    // ldmatrix thread bases
    const uint32_t a_tb = (uint32_t)(((wm + (l & 15)) * AP + ((l >> 4) << 3)) * 2);
    const uint32_t b_tb = (uint32_t)(((l & 15) * BP2 + wn + ((l >> 4) << 3)) * 2);

    float acc[4][4][4];
#pragma unroll
    for (int mi = 0; mi < 4; ++mi)
#pragma unroll
        for (int ni = 0; ni < 4; ++ni)
#pragma unroll
            for (int e = 0; e < 4; ++e) acc[mi][ni][e] = 0.f;

#define ISSUE(ktArg) { \
    const int _st = (ktArg) & (NSTAGE - 1); \
    const uint32_t _ab = sb + _st * STAGE_BYTES; \
    const __half* _ap = arow + (ktArg) * 32 + sgA; \
    const uint32_t _ad = _ab + (uint32_t)(r * AP + sgA) * 2; \
    CP16(_ad, _ap); CP16(_ad + 16, _ap + 8); \
    const uint32_t _bb = _ab + B_OFF; \
    const __half* _bp = Bk + (size_t)((ktArg) * 32 + bK) * 512 + bn + bN; \
    const uint32_t _bd = _bb + (uint32_t)(bK * BP2 + bN) * 2; \
    CP16(_bd, _bp); CP16(_bd + 16, _bp + 8); }

    // prologue: fill NSTAGE-1 stages
#pragma unroll
    for (int ps = 0; ps < NSTAGE - 1; ++ps) {
        if (ps < nkt) ISSUE(ps);
        CPCOMMIT();
    }

    for (int kt = 0; kt < nkt; ++kt) {
        const int buf = kt & (NSTAGE - 1);
        asm volatile("cp.async.wait_group %0;" :: "n"(NSTAGE - 2) : "memory");
        __syncthreads();
        if (kt + NSTAGE - 1 < nkt) ISSUE(kt + NSTAGE - 1);
        CPCOMMIT();

        const uint32_t abase = sb + buf * STAGE_BYTES;
        const uint32_t bbase = abase + B_OFF;

#pragma unroll
        for (int kk = 0; kk < 2; ++kk) {
            uint32_t a[4][4];
#pragma unroll
            for (int mi = 0; mi < 4; ++mi)
                ldsm_x4(abase + a_tb + (uint32_t)(mi * 16 * AP * 2 + kk * 32),
                        a[mi][0], a[mi][1], a[mi][2], a[mi][3]);
            uint32_t b[4][2];
            {
                const uint32_t bk0 = bbase + b_tb + (uint32_t)(kk * 16 * BP2 * 2);
                ldsm_x4_t(bk0,      b[0][0], b[0][1], b[1][0], b[1][1]);
                ldsm_x4_t(bk0 + 32, b[2][0], b[2][1], b[3][0], b[3][1]);
            }
#pragma unroll
            for (int ni = 0; ni < 4; ++ni)
#pragma unroll
                for (int mi = 0; mi < 4; ++mi)
                    mma_f16(acc[mi][ni], a[mi][0], a[mi][1], a[mi][2], a[mi][3],
                            b[ni][0], b[ni][1]);
        }
    }
#undef ISSUE

    __syncthreads();

#pragma unroll
    for (int mi = 0; mi < 4; ++mi) {
        const int r0 = bm + wm + mi * 16 + g;
#pragma unroll
        for (int ni = 0; ni < 4; ++ni) {
            const int cl = wn + ni * 8 + 2 * t;
            const int cn = bn + cl;
            float f0 = acc[mi][ni][0], f1 = acc[mi][ni][1];
            float f2 = acc[mi][ni][2], f3 = acc[mi][ni][3];
            if (BIAS) {
                const float b0 = sbias[cl], b1 = sbias[cl + 1];
                f0 += b0; f1 += b1; f2 += b0; f3 += b1;
            }
            if (OUTHALF) {
                __half* C = (__half*)Cp;
                *(__half2*)&C[(size_t)r0 * ldc + cn] = __floats2half2_rn(f0, f1);
                *(__half2*)&C[(size_t)(r0 + 8) * ldc + cn] = __floats2half2_rn(f2, f3);
            } else {
                float* C = (float*)Cp;
                *(float2*)&C[(size_t)r0 * ldc + cn] = make_float2(f0, f1);
                *(float2*)&C[(size_t)(r0 + 8) * ldc + cn] = make_float2(f2, f3);
            }
        }
    }
}

// ---------------------------------------------------------------------------
// merged qproj + conv kernel: grid 1024
// ---------------------------------------------------------------------------
__global__ void __launch_bounds__(256) qc_tc(const float* __restrict__ bq)
{
    const int bid = blockIdx.x;
    const int r = threadIdx.x >> 1;
    if (bid < 512) {
        const int bm = (bid >> 2) * 128, bn = (bid & 3) * 128;
        const __half* arow = g_xh + (size_t)(bm + r) * 512;
        gemm_core<true, true>(arow, g_wqh, bq, g_qh, 512, 16, bm, bn);
    } else {
        const int c = bid - 512;
        const int z = c >> 5, tl = c & 31;
        const int bm = (tl >> 2) * 128, bn = (tl & 3) * 128;
        const int gr = bm + r;
        const int pix = (gr >> 8) * 4096 + (((gr >> 4) & 15) << 8) + ((gr & 15) << 2);
        const int off = ((z >> 2) << 6) | (z & 3);
        const __half* arow = g_xh + (size_t)(pix + off) * 512;
        gemm_core<false, false>(arow, g_wsrh + (size_t)z * 512 * 512, nullptr,
                                g_xr_part + (size_t)z * (BB * NKV * CC), 512, 16, bm, bn);
    }
}

__global__ void __launch_bounds__(256) kv_tc(const float* __restrict__ bk,
                                             const float* __restrict__ bv)
{
    const int bid = blockIdx.x;
    const int sel = bid >> 5;
    const int tl = bid & 31;
    const int bm = (tl >> 2) * 128, bn = (tl & 3) * 128;
    const __half* arow = g_xrh + (size_t)(bm + (threadIdx.x >> 1)) * 512;
    if (sel == 0)
        gemm_core<true, true>(arow, g_wkh, bk, g_kh, 512, 16, bm, bn);
    else
        gemm_core<true, true>(arow, g_wvh, bv, g_vh, 512, 16, bm, bn);
}

__global__ void __launch_bounds__(256) outproj_tc(const float* __restrict__ bp,
                                                  float* __restrict__ out)
{
    const int bid = blockIdx.x;
    const int bm = (bid >> 2) * 128, bn = (bid & 3) * 128;
    const __half* arow = g_attnh + (size_t)(bm + (threadIdx.x >> 1)) * 512;
    gemm_core<false, true>(arow, g_wph, bp, out, 512, 16, bm, bn);
}

// ---------------------------------------------------------------------------
// Convert x + all weights to fp16 (one flat kernel)
// ---------------------------------------------------------------------------
__global__ void convert_all(const float* __restrict__ x,
                            const float* __restrict__ wq,
                            const float* __restrict__ wk,
                            const float* __restrict__ wv,
                            const float* __restrict__ wp,
                            const float* __restrict__ w_sr)
{
    const size_t cid = (size_t)blockIdx.x * blockDim.x + threadIdx.x;
    const float* src;
    __half* dst;
    size_t loc;
    if (cid < 1048576)        { src = x;    dst = g_xh;  loc = cid; }
    else if (cid < 1081344)   { src = wq;   dst = g_wqh; loc = cid - 1048576; }
    else if (cid < 1114112)   { src = wk;   dst = g_wkh; loc = cid - 1081344; }
    else if (cid < 1146880)   { src = wv;   dst = g_wvh; loc = cid - 1114112; }
    else if (cid < 1179648)   { src = wp;   dst = g_wph; loc = cid - 1146880; }
    else                      { src = w_sr; dst = g_wsrh; loc = cid - 1179648; }
    const size_t i = loc * 8;
    float4 u = *(const float4*)&src[i];
    float4 v = *(const float4*)&src[i + 4];
    __half2 h0 = __floats2half2_rn(u.x, u.y);
    __half2 h1 = __floats2half2_rn(u.z, u.w);
    __half2 h2 = __floats2half2_rn(v.x, v.y);
    __half2 h3 = __floats2half2_rn(v.z, v.w);
    uint4 pk;
    pk.x = *(uint32_t*)&h0; pk.y = *(uint32_t*)&h1;
    pk.z = *(uint32_t*)&h2; pk.w = *(uint32_t*)&h3;
    *(uint4*)&dst[i] = pk;
}

// ---------------------------------------------------------------------------
// split-K reduce + bias + LayerNorm -> fp16
// ---------------------------------------------------------------------------
__global__ void ln_kernel(const float* __restrict__ bsr,
                          const float* __restrict__ gamma,
                          const float* __restrict__ beta)
{
    const int r = blockIdx.x;
    const int tid = threadIdx.x;
    float v[4];
    float s1 = 0.f, s2 = 0.f;
#pragma unroll
    for (int i = 0; i < 4; ++i) {
        const int c = tid + i * 128;
        const size_t off = (size_t)r * 512 + c;
        float tt = bsr[c];
#pragma unroll
        for (int p = 0; p < CSPLIT; ++p)
            tt += g_xr_part[(size_t)p * (BB * NKV * CC) + off];
        v[i] = tt;
        s1 += tt;
        s2 += tt * tt;
    }
#pragma unroll
    for (int o = 16; o > 0; o >>= 1) {
        s1 += __shfl_xor_sync(0xffffffffu, s1, o);
        s2 += __shfl_xor_sync(0xffffffffu, s2, o);
    }
    __shared__ float red[8];
    const int warp = tid >> 5, lane = tid & 31;
    if (lane == 0) { red[warp] = s1; red[warp + 4] = s2; }
    __syncthreads();
    s1 = red[0] + red[1] + red[2] + red[3];
    s2 = red[4] + red[5] + red[6] + red[7];
    const float mu = s1 * (1.f / 512.f);
    const float var = s2 * (1.f / 512.f) - mu * mu;
    const float rstd = rsqrtf(var + 1e-5f);
#pragma unroll
    for (int i = 0; i < 4; ++i) {
        const int c = tid + i * 128;
        g_xrh[(size_t)r * 512 + c] = __float2half((v[i] - mu) * rstd * gamma[c] + beta[c]);
    }
}

// ---------------------------------------------------------------------------
// Attention (unchanged — verified)
// ---------------------------------------------------------------------------
#define QP 72
#define KP 72
#define VP 264
#define SP 264
#define PP 272
#define ATT_SMEM ((4608 + 18432 + 16896) * 2 + 16896 * 4)

__global__ void __launch_bounds__(256) attn_kernel()
{
    extern __shared__ __align__(1024) char smem[];
    __half* Qh = (__half*)smem;
    __half* Kh = Qh + 4608;
    __half* Vh = Qh + 23040;
    float*  S  = (float*)(smem + 79872);
    __half* Ph = Qh;

    const int tid = threadIdx.x;
    const int w = tid >> 5, l = tid & 31;
    const int g = l >> 2, t = l & 3;

    const int bh = blockIdx.y;
    const int b = bh >> 3, h = bh & 7;
    const int q0 = blockIdx.x * 64;
    const size_t qbase  = ((size_t)(b * NQ + q0)) * CC + h * DH;
    const size_t kvbase = ((size_t)(b * NKV)) * CC + h * DH;

#pragma unroll
    for (int i = 0; i < 2; ++i) {
        const int c = tid + i * 256;
        const int r = c >> 3, seg = (c & 7) * 8;
        *(uint4*)&Qh[r * QP + seg] = *(const uint4*)&g_qh[qbase + (size_t)r * CC + seg];
    }
#pragma unroll
    for (int i = 0; i < 8; ++i) {
        const int c = tid + i * 256;
        const int r = c >> 3, seg = (c & 7) * 8;
        *(uint4*)&Kh[r * KP + seg] = *(const uint4*)&g_kh[kvbase + (size_t)r * CC + seg];
    }
#pragma unroll
    for (int i = 0; i < 8; ++i) {
        const int c = tid + i * 256;
        const int kv = c >> 3, d0 = (c & 7) * 8;
        uint4 pk = *(const uint4*)&g_vh[kvbase + (size_t)kv * CC + d0];
        const __half* hv = (const __half*)&pk;
#pragma unroll
        for (int j = 0; j < 8; ++j)
            Vh[(d0 + j) * VP + kv] = hv[j];
    }
    __syncthreads();

    {
        const int wm = (w >> 2) * 32;
        const int wn = (w & 3) * 64;
        float accS[2][8][4];
#pragma unroll
        for (int mi = 0; mi < 2; ++mi)
#pragma unroll
            for (int ni = 0; ni < 8; ++ni)
#pragma unroll
                for (int e = 0; e < 4; ++e) accS[mi][ni][e] = 0.f;

#pragma unroll
        for (int kk = 0; kk < 4; ++kk) {
            const int k0 = kk * 16;
            uint32_t a[2][4];
#pragma unroll
            for (int mi = 0; mi < 2; ++mi) {
                const int rr = wm + mi * 16 + g;
                a[mi][0] = *(const uint32_t*)&Qh[rr * QP + k0 + 2 * t];
                a[mi][1] = *(const uint32_t*)&Qh[(rr + 8) * QP + k0 + 2 * t];
                a[mi][2] = *(const uint32_t*)&Qh[rr * QP + k0 + 2 * t + 8];
                a[mi][3] = *(const uint32_t*)&Qh[(rr + 8) * QP + k0 + 2 * t + 8];
            }
#pragma unroll
            for (int ni = 0; ni < 8; ++ni) {
                const int n = wn + ni * 8 + g;
                const uint32_t b0 = *(const uint32_t*)&Kh[n * KP + k0 + 2 * t];
                const uint32_t b1 = *(const uint32_t*)&Kh[n * KP + k0 + 2 * t + 8];
#pragma unroll
                for (int mi = 0; mi < 2; ++mi)
                    mma_f16(accS[mi][ni], a[mi][0], a[mi][1], a[mi][2], a[mi][3], b0, b1);
            }
        }
        const float sc = 0.125f;
#pragma unroll
        for (int mi = 0; mi < 2; ++mi) {
            const int rr = wm + mi * 16 + g;
#pragma unroll
            for (int ni = 0; ni < 8; ++ni) {
                const int cn = wn + ni * 8 + 2 * t;
                *(float2*)&S[rr * SP + cn] = make_float2(accS[mi][ni][0] * sc, accS[mi][ni][1] * sc);
                *(float2*)&S[(rr + 8) * SP + cn] = make_float2(accS[mi][ni][2] * sc, accS[mi][ni][3] * sc);
            }
        }
    }
    __syncthreads();

    for (int r = w; r < 64; r += 8) {
        float* row = &S[r * SP];
        float m = -1e30f;
#pragma unroll
        for (int j = 0; j < 8; ++j) m = fmaxf(m, row[l + j * 32]);
#pragma unroll
        for (int o = 16; o > 0; o >>= 1) m = fmaxf(m, __shfl_xor_sync(0xffffffffu, m, o));
        float s = 0.f;
        float e[8];
#pragma unroll
        for (int j = 0; j < 8; ++j) {
            e[j] = __expf(row[l + j * 32] - m);
            s += e[j];
        }
#pragma unroll
        for (int o = 16; o > 0; o >>= 1) s += __shfl_xor_sync(0xffffffffu, s, o);
        const float inv = 1.f / s;
#pragma unroll
        for (int j = 0; j < 8; ++j)
            Ph[r * PP + l + j * 32] = __float2half(e[j] * inv);
    }
    __syncthreads();

    {
        const int wm = (w >> 2) * 32;
        const int wn = (w & 3) * 16;
        float accO[2][2][4];
#pragma unroll
        for (int mi = 0; mi < 2; ++mi)
#pragma unroll
            for (int ni = 0; ni < 2; ++ni)
#pragma unroll
                for (int e2 = 0; e2 < 4; ++e2) accO[mi][ni][e2] = 0.f;

#pragma unroll
        for (int kk = 0; kk < 16; ++kk) {
            const int k0 = kk * 16;
            uint32_t a[2][4];
#pragma unroll
            for (int mi = 0; mi < 2; ++mi) {
                const int rr = wm + mi * 16 + g;
                a[mi][0] = *(const uint32_t*)&Ph[rr * PP + k0 + 2 * t];
                a[mi][1] = *(const uint32_t*)&Ph[(rr + 8) * PP + k0 + 2 * t];
                a[mi][2] = *(const uint32_t*)&Ph[rr * PP + k0 + 2 * t + 8];
                a[mi][3] = *(const uint32_t*)&Ph[(rr + 8) * PP + k0 + 2 * t + 8];
            }
#pragma unroll
            for (int ni = 0; ni < 2; ++ni) {
                const int n = wn + ni * 8 + g;
                const uint32_t b0 = *(const uint32_t*)&Vh[n * VP + k0 + 2 * t];
                const uint32_t b1 = *(const uint32_t*)&Vh[n * VP + k0 + 2 * t + 8];
#pragma unroll
                for (int mi = 0; mi < 2; ++mi)
                    mma_f16(accO[mi][ni], a[mi][0], a[mi][1], a[mi][2], a[mi][3], b0, b1);
            }
        }
#pragma unroll
        for (int mi = 0; mi < 2; ++mi) {
            const int rr = wm + mi * 16 + g;
#pragma unroll
            for (int ni = 0; ni < 2; ++ni) {
                const int cn = wn + ni * 8 + 2 * t;
                *(__half2*)&g_attnh[qbase + (size_t)rr * CC + cn] =
                    __floats2half2_rn(accO[mi][ni][0], accO[mi][ni][1]);
                *(__half2*)&g_attnh[qbase + (size_t)(rr + 8) * CC + cn] =
                    __floats2half2_rn(accO[mi][ni][2], accO[mi][ni][3]);
            }
        }
    }
}

// ---------------------------------------------------------------------------
extern "C" void kernel_launch(void* const* d_in, const int* in_sizes, int n_in,
                              void* d_out, int out_size)
{
    (void)in_sizes; (void)n_in; (void)out_size;
    const float* x     = (const float*)d_in[0];
    const float* wq    = (const float*)d_in[1];
    const float* bq    = (const float*)d_in[2];
    const float* wk    = (const float*)d_in[3];
    const float* bk    = (const float*)d_in[4];
    const float* wv    = (const float*)d_in[5];
    const float* bv    = (const float*)d_in[6];
    const float* w_sr  = (const float*)d_in[7];
    const float* b_sr  = (const float*)d_in[8];
    const float* gamma = (const float*)d_in[9];
    const float* beta  = (const float*)d_in[10];
    const float* wp    = (const float*)d_in[11];
    const float* bp    = (const float*)d_in[12];
    float* out = (float*)d_out;

    cudaFuncSetAttribute(qc_tc,      cudaFuncAttributeMaxDynamicSharedMemorySize, GEMM_SMEM);
    cudaFuncSetAttribute(kv_tc,      cudaFuncAttributeMaxDynamicSharedMemorySize, GEMM_SMEM);
    cudaFuncSetAttribute(outproj_tc, cudaFuncAttributeMaxDynamicSharedMemorySize, GEMM_SMEM);
    cudaFuncSetAttribute(attn_kernel, cudaFuncAttributeMaxDynamicSharedMemorySize, ATT_SMEM);

    convert_all<<<6656, 256>>>(x, wq, wk, wv, wp, w_sr);
    qc_tc<<<1024, 256, GEMM_SMEM>>>(bq);
    ln_kernel<<<BB * NKV, 128>>>(b_sr, gamma, beta);
    kv_tc<<<64, 256, GEMM_SMEM>>>(bk, bv);
    attn_kernel<<<dim3(NQ / 64, BB * HEADS), 256, ATT_SMEM>>>();
    outproj_tc<<<512, 256, GEMM_SMEM>>>(bp, out);
}

// round 11
// speedup vs baseline: 4.8544x; 1.0136x over previous
#include <cuda_runtime.h>
#include <cuda_fp16.h>
#include <math.h>
#include <stdint.h>

#define BB    4
#define NQ    4096
#define CC    512
#define HEADS 8
#define DH    64
#define NKV   256
#define KCONV 8192
#define CSPLIT 16

// ---------------------------------------------------------------------------
// Scratch
// ---------------------------------------------------------------------------
__device__ __half g_xh[BB * NQ * CC];
__device__ __half g_qh[BB * NQ * CC];
__device__ __half g_kh[BB * NKV * CC];
__device__ __half g_vh[BB * NKV * CC];
__device__ __half g_attnh[BB * NQ * CC];
__device__ __half g_xrh[BB * NKV * CC];
__device__ float  g_xr_part[CSPLIT * BB * NKV * CC];
__device__ __half g_wqh[CC * CC];
__device__ __half g_wkh[CC * CC];
__device__ __half g_wvh[CC * CC];
__device__ __half g_wph[CC * CC];
__device__ __half g_wsrh[(size_t)KCONV * CC];

// ---------------------------------------------------------------------------
// helpers
// ---------------------------------------------------------------------------
__device__ __forceinline__ void mma_f16(float* c,
    uint32_t a0, uint32_t a1, uint32_t a2, uint32_t a3, uint32_t b0, uint32_t b1)
{
    asm volatile(
        "mma.sync.aligned.m16n8k16.row.col.f32.f16.f16.f32 "
        "{%0,%1,%2,%3},{%4,%5,%6,%7},{%8,%9},{%0,%1,%2,%3};"
        : "+f"(c[0]), "+f"(c[1]), "+f"(c[2]), "+f"(c[3])
        : "r"(a0), "r"(a1), "r"(a2), "r"(a3), "r"(b0), "r"(b1));
}

__device__ __forceinline__ void ldsm_x4(uint32_t addr,
    uint32_t& r0, uint32_t& r1, uint32_t& r2, uint32_t& r3)
{
    asm volatile("ldmatrix.sync.aligned.m8n8.x4.shared.b16 {%0,%1,%2,%3}, [%4];"
        : "=r"(r0), "=r"(r1), "=r"(r2), "=r"(r3) : "r"(addr));
}

__device__ __forceinline__ void ldsm_x4_t(uint32_t addr,
    uint32_t& r0, uint32_t& r1, uint32_t& r2, uint32_t& r3)
{
    asm volatile("ldmatrix.sync.aligned.m8n8.x4.trans.shared.b16 {%0,%1,%2,%3}, [%4];"
        : "=r"(r0), "=r"(r1), "=r"(r2), "=r"(r3) : "r"(addr));
}

__device__ __forceinline__ uint32_t smem_u32(const void* p) {
    uint32_t a;
    asm("{ .reg .u64 t; cvta.to.shared.u64 t, %1; cvt.u32.u64 %0, t; }" : "=r"(a) : "l"(p));
    return a;
}

#define CP16(dst, src) \
    asm volatile("cp.async.cg.shared.global [%0], [%1], 16;" :: "r"(dst), "l"(src))
#define CPCOMMIT() asm volatile("cp.async.commit_group;" ::: "memory")

// ---------------------------------------------------------------------------
// fp16 GEMM core: 128x128 tile, K-step 64, 3-stage cp.async, all-fp16 smem.
// A fragments: ldmatrix; B fragments: ldmatrix.trans on [k][n] tile.
// 256 threads = 8 warps, warp grid 2(m) x 4(n), warp tile 64x32.
// ---------------------------------------------------------------------------
#define NSTAGE 3
#define AP   72
#define BP2  136
#define A_BYTES (128 * AP * 2)                 // 18432
#define B_OFF   A_BYTES
#define STAGE_BYTES (A_BYTES + 64 * BP2 * 2)   // 18432 + 17408 = 35840
#define GEMM_SMEM (NSTAGE * STAGE_BYTES + 512) // 108032

template<bool OUTHALF, bool BIAS>
__device__ __forceinline__ void gemm_core(
    const __half* __restrict__ arow,   // per-thread A row base (row = tid>>1)
    const __half* __restrict__ Bk,     // fp16 B base: [k][512]
    const float* __restrict__ bias,
    void* __restrict__ Cp, int ldc,
    int nkt, int bm, int bn)           // nkt counts K-steps of 64
{
    extern __shared__ __align__(16) char smem[];
    float* sbias = (float*)(smem + NSTAGE * STAGE_BYTES);

    const int tid = threadIdx.x;
    const int w = tid >> 5, l = tid & 31;
    const int g = l >> 2, t = l & 3;
    const int wm = (w >> 2) * 64;
    const int wn = (w & 3) * 32;

    if (BIAS && tid < 128) sbias[tid] = bias[bn + tid];

    // A staging: row = tid>>1 (0..127), thread covers halves [segA, segA+32)
    const int segA = (tid & 1) * 32;
    // B staging: bK = tid>>2 (0..63), thread covers halves [bN, bN+32)
    const int bK = tid >> 2;
    const int bN = (tid & 3) * 32;
    const uint32_t sb = smem_u32(smem);
    const uint32_t a_tb = (uint32_t)(((wm + (l & 15)) * AP + ((l >> 4) << 3)) * 2);
    const uint32_t b_tb = (uint32_t)(((l & 15) * BP2 + wn + ((l >> 4) << 3)) * 2);

    float acc[4][4][4];
#pragma unroll
    for (int mi = 0; mi < 4; ++mi)
#pragma unroll
        for (int ni = 0; ni < 4; ++ni)
#pragma unroll
            for (int e = 0; e < 4; ++e) acc[mi][ni][e] = 0.f;

// Each stage: A 1024 chunks + B 1024 chunks -> 4 + 4 CP16 per thread.
#define ISSUE(ktArg, stArg) { \
    const uint32_t _ab = sb + (stArg) * STAGE_BYTES; \
    const __half* _ap = arow + (ktArg) * 64 + segA; \
    const uint32_t _ad = _ab + (uint32_t)((tid >> 1) * AP + segA) * 2; \
    CP16(_ad,      _ap);      CP16(_ad + 16, _ap + 8); \
    CP16(_ad + 32, _ap + 16); CP16(_ad + 48, _ap + 24); \
    const uint32_t _bb = _ab + B_OFF; \
    const __half* _bp = Bk + (size_t)((ktArg) * 64 + bK) * 512 + bn + bN; \
    const uint32_t _bd = _bb + (uint32_t)(bK * BP2 + bN) * 2; \
    CP16(_bd,      _bp);      CP16(_bd + 16, _bp + 8); \
    CP16(_bd + 32, _bp + 16); CP16(_bd + 48, _bp + 24); }

    // prologue: stages 0,1
    ISSUE(0, 0); CPCOMMIT();
    if (nkt > 1) ISSUE(1, 1);
    CPCOMMIT();

    int buf = 0, nxt = 2;
    for (int kt = 0; kt < nkt; ++kt) {
        asm volatile("cp.async.wait_group 1;" ::: "memory");
        __syncthreads();
        if (kt + 2 < nkt) ISSUE(kt + 2, nxt);
        CPCOMMIT();

        const uint32_t abase = sb + buf * STAGE_BYTES;
        const uint32_t bbase = abase + B_OFF;

#pragma unroll
        for (int kk = 0; kk < 4; ++kk) {
            uint32_t a[4][4];
#pragma unroll
            for (int mi = 0; mi < 4; ++mi)
                ldsm_x4(abase + a_tb + (uint32_t)(mi * 16 * AP * 2 + kk * 32),
                        a[mi][0], a[mi][1], a[mi][2], a[mi][3]);
            uint32_t b[4][2];
            {
                const uint32_t bk0 = bbase + b_tb + (uint32_t)(kk * 16 * BP2 * 2);
                ldsm_x4_t(bk0,      b[0][0], b[0][1], b[1][0], b[1][1]);
                ldsm_x4_t(bk0 + 32, b[2][0], b[2][1], b[3][0], b[3][1]);
            }
#pragma unroll
            for (int ni = 0; ni < 4; ++ni)
#pragma unroll
                for (int mi = 0; mi < 4; ++mi)
                    mma_f16(acc[mi][ni], a[mi][0], a[mi][1], a[mi][2], a[mi][3],
                            b[ni][0], b[ni][1]);
        }
        buf = (buf == 2) ? 0 : buf + 1;
        nxt = (nxt == 2) ? 0 : nxt + 1;
    }
#undef ISSUE

    __syncthreads();

#pragma unroll
    for (int mi = 0; mi < 4; ++mi) {
        const int r0 = bm + wm + mi * 16 + g;
#pragma unroll
        for (int ni = 0; ni < 4; ++ni) {
            const int cl = wn + ni * 8 + 2 * t;
            const int cn = bn + cl;
            float f0 = acc[mi][ni][0], f1 = acc[mi][ni][1];
            float f2 = acc[mi][ni][2], f3 = acc[mi][ni][3];
            if (BIAS) {
                const float b0 = sbias[cl], b1 = sbias[cl + 1];
                f0 += b0; f1 += b1; f2 += b0; f3 += b1;
            }
            if (OUTHALF) {
                __half* C = (__half*)Cp;
                *(__half2*)&C[(size_t)r0 * ldc + cn] = __floats2half2_rn(f0, f1);
                *(__half2*)&C[(size_t)(r0 + 8) * ldc + cn] = __floats2half2_rn(f2, f3);
            } else {
                float* C = (float*)Cp;
                *(float2*)&C[(size_t)r0 * ldc + cn] = make_float2(f0, f1);
                *(float2*)&C[(size_t)(r0 + 8) * ldc + cn] = make_float2(f2, f3);
            }
        }
    }
}

// ---------------------------------------------------------------------------
// merged qproj + conv kernel: grid 1024
// ---------------------------------------------------------------------------
__global__ void __launch_bounds__(256) qc_tc(const float* __restrict__ bq)
{
    const int bid = blockIdx.x;
    const int r = threadIdx.x >> 1;
    if (bid < 512) {
        const int bm = (bid >> 2) * 128, bn = (bid & 3) * 128;
        const __half* arow = g_xh + (size_t)(bm + r) * 512;
        gemm_core<true, true>(arow, g_wqh, bq, g_qh, 512, 8, bm, bn);
    } else {
        const int c = bid - 512;
        const int z = c >> 5, tl = c & 31;
        const int bm = (tl >> 2) * 128, bn = (tl & 3) * 128;
        const int gr = bm + r;
        const int pix = (gr >> 8) * 4096 + (((gr >> 4) & 15) << 8) + ((gr & 15) << 2);
        const int off = ((z >> 2) << 6) | (z & 3);
        const __half* arow = g_xh + (size_t)(pix + off) * 512;
        gemm_core<false, false>(arow, g_wsrh + (size_t)z * 512 * 512, nullptr,
                                g_xr_part + (size_t)z * (BB * NKV * CC), 512, 8, bm, bn);
    }
}

__global__ void __launch_bounds__(256) kv_tc(const float* __restrict__ bk,
                                             const float* __restrict__ bv)
{
    const int bid = blockIdx.x;
    const int sel = bid >> 5;
    const int tl = bid & 31;
    const int bm = (tl >> 2) * 128, bn = (tl & 3) * 128;
    const __half* arow = g_xrh + (size_t)(bm + (threadIdx.x >> 1)) * 512;
    if (sel == 0)
        gemm_core<true, true>(arow, g_wkh, bk, g_kh, 512, 8, bm, bn);
    else
        gemm_core<true, true>(arow, g_wvh, bv, g_vh, 512, 8, bm, bn);
}

__global__ void __launch_bounds__(256) outproj_tc(const float* __restrict__ bp,
                                                  float* __restrict__ out)
{
    const int bid = blockIdx.x;
    const int bm = (bid >> 2) * 128, bn = (bid & 3) * 128;
    const __half* arow = g_attnh + (size_t)(bm + (threadIdx.x >> 1)) * 512;
    gemm_core<false, true>(arow, g_wph, bp, out, 512, 8, bm, bn);
}

// ---------------------------------------------------------------------------
// Convert x + all weights to fp16 (one flat kernel)
// ---------------------------------------------------------------------------
__global__ void convert_all(const float* __restrict__ x,
                            const float* __restrict__ wq,
                            const float* __restrict__ wk,
                            const float* __restrict__ wv,
                            const float* __restrict__ wp,
                            const float* __restrict__ w_sr)
{
    const size_t cid = (size_t)blockIdx.x * blockDim.x + threadIdx.x;
    const float* src;
    __half* dst;
    size_t loc;
    if (cid < 1048576)        { src = x;    dst = g_xh;  loc = cid; }
    else if (cid < 1081344)   { src = wq;   dst = g_wqh; loc = cid - 1048576; }
    else if (cid < 1114112)   { src = wk;   dst = g_wkh; loc = cid - 1081344; }
    else if (cid < 1146880)   { src = wv;   dst = g_wvh; loc = cid - 1114112; }
    else if (cid < 1179648)   { src = wp;   dst = g_wph; loc = cid - 1146880; }
    else                      { src = w_sr; dst = g_wsrh; loc = cid - 1179648; }
    const size_t i = loc * 8;
    float4 u = *(const float4*)&src[i];
    float4 v = *(const float4*)&src[i + 4];
    __half2 h0 = __floats2half2_rn(u.x, u.y);
    __half2 h1 = __floats2half2_rn(u.z, u.w);
    __half2 h2 = __floats2half2_rn(v.x, v.y);
    __half2 h3 = __floats2half2_rn(v.z, v.w);
    uint4 pk;
    pk.x = *(uint32_t*)&h0; pk.y = *(uint32_t*)&h1;
    pk.z = *(uint32_t*)&h2; pk.w = *(uint32_t*)&h3;
    *(uint4*)&dst[i] = pk;
}

// ---------------------------------------------------------------------------
// split-K reduce + bias + LayerNorm -> fp16
// ---------------------------------------------------------------------------
__global__ void ln_kernel(const float* __restrict__ bsr,
                          const float* __restrict__ gamma,
                          const float* __restrict__ beta)
{
    const int r = blockIdx.x;
    const int tid = threadIdx.x;
    float v[4];
    float s1 = 0.f, s2 = 0.f;
#pragma unroll
    for (int i = 0; i < 4; ++i) {
        const int c = tid + i * 128;
        const size_t off = (size_t)r * 512 + c;
        float tt = bsr[c];
#pragma unroll
        for (int p = 0; p < CSPLIT; ++p)
            tt += g_xr_part[(size_t)p * (BB * NKV * CC) + off];
        v[i] = tt;
        s1 += tt;
        s2 += tt * tt;
    }
#pragma unroll
    for (int o = 16; o > 0; o >>= 1) {
        s1 += __shfl_xor_sync(0xffffffffu, s1, o);
        s2 += __shfl_xor_sync(0xffffffffu, s2, o);
    }
    __shared__ float red[8];
    const int warp = tid >> 5, lane = tid & 31;
    if (lane == 0) { red[warp] = s1; red[warp + 4] = s2; }
    __syncthreads();
    s1 = red[0] + red[1] + red[2] + red[3];
    s2 = red[4] + red[5] + red[6] + red[7];
    const float mu = s1 * (1.f / 512.f);
    const float var = s2 * (1.f / 512.f) - mu * mu;
    const float rstd = rsqrtf(var + 1e-5f);
#pragma unroll
    for (int i = 0; i < 4; ++i) {
        const int c = tid + i * 128;
        g_xrh[(size_t)r * 512 + c] = __float2half((v[i] - mu) * rstd * gamma[c] + beta[c]);
    }
}

// ---------------------------------------------------------------------------
// Attention: cp.async loads, V natural + ldmatrix.trans for PV.
// smem: Q [64][72]h @0 | K [256][72]h @9216 | V [256][72]h @46080 |
//       S [64][264]f @82944 ; Ph [64][272]h aliases Q/K region.
// ---------------------------------------------------------------------------
#define QP 72
#define KP 72
#define VP 72
#define SP 264
#define PP 272
#define ATT_K0 9216
#define ATT_V0 46080
#define ATT_S0 82944
#define ATT_SMEM 150528

__global__ void __launch_bounds__(256) attn_kernel()
{
    extern __shared__ __align__(16) char smem[];
    __half* Qh = (__half*)smem;
    __half* Kh = (__half*)(smem + ATT_K0);
    float*  S  = (float*)(smem + ATT_S0);
    __half* Ph = (__half*)smem;

    const int tid = threadIdx.x;
    const int w = tid >> 5, l = tid & 31;
    const int g = l >> 2, t = l & 3;
    const uint32_t sbA = smem_u32(smem);

    const int bh = blockIdx.y;
    const int b = bh >> 3, h = bh & 7;
    const int q0 = blockIdx.x * 64;
    const size_t qbase  = ((size_t)(b * NQ + q0)) * CC + h * DH;
    const size_t kvbase = ((size_t)(b * NKV)) * CC + h * DH;

    // Q + K via cp.async (group 1)
#pragma unroll
    for (int i = 0; i < 2; ++i) {
        const int c = tid + i * 256;
        const int r = c >> 3, seg = (c & 7) * 8;
        CP16(sbA + (uint32_t)(r * QP + seg) * 2, &g_qh[qbase + (size_t)r * CC + seg]);
    }
#pragma unroll
    for (int i = 0; i < 8; ++i) {
        const int c = tid + i * 256;
        const int r = c >> 3, seg = (c & 7) * 8;
        CP16(sbA + ATT_K0 + (uint32_t)(r * KP + seg) * 2, &g_kh[kvbase + (size_t)r * CC + seg]);
    }
    CPCOMMIT();
    // V natural via cp.async (group 2) — overlaps with S compute
#pragma unroll
    for (int i = 0; i < 8; ++i) {
        const int c = tid + i * 256;
        const int r = c >> 3, seg = (c & 7) * 8;
        CP16(sbA + ATT_V0 + (uint32_t)(r * VP + seg) * 2, &g_vh[kvbase + (size_t)r * CC + seg]);
    }
    CPCOMMIT();
    asm volatile("cp.async.wait_group 1;" ::: "memory");
    __syncthreads();

    // S = Q K^T * scale : warps 2m x 4n, warp tile 32x64
    {
        const int wm = (w >> 2) * 32;
        const int wn = (w & 3) * 64;
        float accS[2][8][4];
#pragma unroll
        for (int mi = 0; mi < 2; ++mi)
#pragma unroll
            for (int ni = 0; ni < 8; ++ni)
#pragma unroll
                for (int e = 0; e < 4; ++e) accS[mi][ni][e] = 0.f;

#pragma unroll
        for (int kk = 0; kk < 4; ++kk) {
            const int k0 = kk * 16;
            uint32_t a[2][4];
#pragma unroll
            for (int mi = 0; mi < 2; ++mi) {
                const int rr = wm + mi * 16 + g;
                a[mi][0] = *(const uint32_t*)&Qh[rr * QP + k0 + 2 * t];
                a[mi][1] = *(const uint32_t*)&Qh[(rr + 8) * QP + k0 + 2 * t];
                a[mi][2] = *(const uint32_t*)&Qh[rr * QP + k0 + 2 * t + 8];
                a[mi][3] = *(const uint32_t*)&Qh[(rr + 8) * QP + k0 + 2 * t + 8];
            }
#pragma unroll
            for (int ni = 0; ni < 8; ++ni) {
                const int n = wn + ni * 8 + g;
                const uint32_t b0 = *(const uint32_t*)&Kh[n * KP + k0 + 2 * t];
                const uint32_t b1 = *(const uint32_t*)&Kh[n * KP + k0 + 2 * t + 8];
#pragma unroll
                for (int mi = 0; mi < 2; ++mi)
                    mma_f16(accS[mi][ni], a[mi][0], a[mi][1], a[mi][2], a[mi][3], b0, b1);
            }
        }
        const float sc = 0.125f;
#pragma unroll
        for (int mi = 0; mi < 2; ++mi) {
            const int rr = wm + mi * 16 + g;
#pragma unroll
            for (int ni = 0; ni < 8; ++ni) {
                const int cn = wn + ni * 8 + 2 * t;
                *(float2*)&S[rr * SP + cn] = make_float2(accS[mi][ni][0] * sc, accS[mi][ni][1] * sc);
                *(float2*)&S[(rr + 8) * SP + cn] = make_float2(accS[mi][ni][2] * sc, accS[mi][ni][3] * sc);
            }
        }
    }
    asm volatile("cp.async.wait_group 0;" ::: "memory");
    __syncthreads();

    // softmax -> Ph (aliases Q/K region)
    for (int r = w; r < 64; r += 8) {
        float* row = &S[r * SP];
        float m = -1e30f;
#pragma unroll
        for (int j = 0; j < 8; ++j) m = fmaxf(m, row[l + j * 32]);
#pragma unroll
        for (int o = 16; o > 0; o >>= 1) m = fmaxf(m, __shfl_xor_sync(0xffffffffu, m, o));
        float s = 0.f;
        float e[8];
#pragma unroll
        for (int j = 0; j < 8; ++j) {
            e[j] = __expf(row[l + j * 32] - m);
            s += e[j];
        }
#pragma unroll
        for (int o = 16; o > 0; o >>= 1) s += __shfl_xor_sync(0xffffffffu, s, o);
        const float inv = 1.f / s;
#pragma unroll
        for (int j = 0; j < 8; ++j)
            Ph[r * PP + l + j * 32] = __float2half(e[j] * inv);
    }
    __syncthreads();

    // O = P @ V : warps 2m x 4n, warp tile 32x16; B frags via ldsm.trans on V natural
    {
        const int wm = (w >> 2) * 32;
        const int wn = (w & 3) * 16;
        float accO[2][2][4];
#pragma unroll
        for (int mi = 0; mi < 2; ++mi)
#pragma unroll
            for (int ni = 0; ni < 2; ++ni)
#pragma unroll
                for (int e2 = 0; e2 < 4; ++e2) accO[mi][ni][e2] = 0.f;

        const uint32_t v_tb = sbA + ATT_V0 +
            (uint32_t)(((l & 15) * VP + wn + ((l >> 4) << 3)) * 2);

#pragma unroll
        for (int kk = 0; kk < 16; ++kk) {
            const int k0 = kk * 16;
            uint32_t a[2][4];
#pragma unroll
            for (int mi = 0; mi < 2; ++mi) {
                const int rr = wm + mi * 16 + g;
                a[mi][0] = *(const uint32_t*)&Ph[rr * PP + k0 + 2 * t];
                a[mi][1] = *(const uint32_t*)&Ph[(rr + 8) * PP + k0 + 2 * t];
                a[mi][2] = *(const uint32_t*)&Ph[rr * PP + k0 + 2 * t + 8];
                a[mi][3] = *(const uint32_t*)&Ph[(rr + 8) * PP + k0 + 2 * t + 8];
            }
            uint32_t b00, b01, b10, b11;
            ldsm_x4_t(v_tb + (uint32_t)(k0 * VP * 2), b00, b01, b10, b11);
#pragma unroll
            for (int mi = 0; mi < 2; ++mi) {
                mma_f16(accO[mi][0], a[mi][0], a[mi][1], a[mi][2], a[mi][3], b00, b01);
                mma_f16(accO[mi][1], a[mi][0], a[mi][1], a[mi][2], a[mi][3], b10, b11);
            }
        }
#pragma unroll
        for (int mi = 0; mi < 2; ++mi) {
            const int rr = wm + mi * 16 + g;
#pragma unroll
            for (int ni = 0; ni < 2; ++ni) {
                const int cn = wn + ni * 8 + 2 * t;
                *(__half2*)&g_attnh[qbase + (size_t)rr * CC + cn] =
                    __floats2half2_rn(accO[mi][ni][0], accO[mi][ni][1]);
                *(__half2*)&g_attnh[qbase + (size_t)(rr + 8) * CC + cn] =
                    __floats2half2_rn(accO[mi][ni][2], accO[mi][ni][3]);
            }
        }
    }
}

// ---------------------------------------------------------------------------
extern "C" void kernel_launch(void* const* d_in, const int* in_sizes, int n_in,
                              void* d_out, int out_size)
{
    (void)in_sizes; (void)n_in; (void)out_size;
    const float* x     = (const float*)d_in[0];
    const float* wq    = (const float*)d_in[1];
    const float* bq    = (const float*)d_in[2];
    const float* wk    = (const float*)d_in[3];
    const float* bk    = (const float*)d_in[4];
    const float* wv    = (const float*)d_in[5];
    const float* bv    = (const float*)d_in[6];
    const float* w_sr  = (const float*)d_in[7];
    const float* b_sr  = (const float*)d_in[8];
    const float* gamma = (const float*)d_in[9];
    const float* beta  = (const float*)d_in[10];
    const float* wp    = (const float*)d_in[11];
    const float* bp    = (const float*)d_in[12];
    float* out = (float*)d_out;

    cudaFuncSetAttribute(qc_tc,      cudaFuncAttributeMaxDynamicSharedMemorySize, GEMM_SMEM);
    cudaFuncSetAttribute(kv_tc,      cudaFuncAttributeMaxDynamicSharedMemorySize, GEMM_SMEM);
    cudaFuncSetAttribute(outproj_tc, cudaFuncAttributeMaxDynamicSharedMemorySize, GEMM_SMEM);
    cudaFuncSetAttribute(attn_kernel, cudaFuncAttributeMaxDynamicSharedMemorySize, ATT_SMEM);

    convert_all<<<6656, 256>>>(x, wq, wk, wv, wp, w_sr);
    qc_tc<<<1024, 256, GEMM_SMEM>>>(bq);
    ln_kernel<<<BB * NKV, 128>>>(b_sr, gamma, beta);
    kv_tc<<<64, 256, GEMM_SMEM>>>(bk, bv);
    attn_kernel<<<dim3(NQ / 64, BB * HEADS), 256, ATT_SMEM>>>();
    outproj_tc<<<512, 256, GEMM_SMEM>>>(bp, out);
}